// round 2
// baseline (speedup 1.0000x reference)
#include <cuda_runtime.h>
#include <cuda_bf16.h>
#include <cstdint>

#define N_NODES 50000
#define N_EDGES 800000
#define F_IN    64
#define F_MID   128

// ---------------- scratch (device globals; no allocations) ----------------
__device__ int   g_deg_out[N_NODES];
__device__ int   g_deg_in [N_NODES];
__device__ float g_norm_src[N_NODES];
__device__ float g_norm_dst[N_NODES];
__device__ float g_agg1[(size_t)N_NODES * F_IN];    // 12.8 MB
__device__ float g_h1  [(size_t)N_NODES * F_MID];   // 25.6 MB
__device__ float g_t2  [(size_t)N_NODES * F_IN];    // 12.8 MB

// ---------------- kernels ----------------

// Zero degrees, agg1, and d_out (used as the layer-2 accumulator).
__global__ void zero_kernel(float* __restrict__ out) {
    int i = blockIdx.x * blockDim.x + threadIdx.x;   // 0 .. N_NODES*F_IN-1
    if (i < N_NODES * F_IN) {
        g_agg1[i] = 0.f;
        out[i]    = 0.f;
    }
    if (i < N_NODES) {
        g_deg_out[i] = 0;
        g_deg_in[i]  = 0;
    }
}

__global__ void degree_kernel(const int* __restrict__ src,
                              const int* __restrict__ dst) {
    int e = blockIdx.x * blockDim.x + threadIdx.x;
    if (e >= N_EDGES) return;
    atomicAdd(&g_deg_out[src[e]], 1);
    atomicAdd(&g_deg_in [dst[e]], 1);
}

__global__ void norm_kernel() {
    int i = blockIdx.x * blockDim.x + threadIdx.x;
    if (i >= N_NODES) return;
    g_norm_src[i] = rsqrtf(fmaxf((float)g_deg_out[i], 1.f));
    g_norm_dst[i] = rsqrtf(fmaxf((float)g_deg_in [i], 1.f));
}

__device__ __forceinline__ void red_add_v4(float* p, float4 v) {
    asm volatile("red.global.add.v4.f32 [%0], {%1,%2,%3,%4};"
                 :: "l"(p), "f"(v.x), "f"(v.y), "f"(v.z), "f"(v.w)
                 : "memory");
}

// Layer-1 scatter: agg1[dst] += h[src] * norm_src[src].  16 lanes / edge (float4 each).
__global__ void scatter1_kernel(const float* __restrict__ h,
                                const int* __restrict__ src,
                                const int* __restrict__ dst) {
    long long tid = (long long)blockIdx.x * blockDim.x + threadIdx.x;
    int e = (int)(tid >> 4);
    if (e >= N_EDGES) return;
    int c = ((int)tid & 15) << 2;
    int s = src[e], d = dst[e];
    float ns = g_norm_src[s];
    float4 v = *reinterpret_cast<const float4*>(h + (size_t)s * F_IN + c);
    v.x *= ns; v.y *= ns; v.z *= ns; v.w *= ns;
    red_add_v4(g_agg1 + (size_t)d * F_IN + c, v);
}

// h1 = relu(norm_dst ⊙ (agg1 @ W1) + b1)   — W1: [64,128] in smem, 8 rows/block.
__global__ __launch_bounds__(256) void gemm1_kernel(const float* __restrict__ W1,
                                                    const float* __restrict__ b1) {
    __shared__ float Ws[F_IN * F_MID];   // 32 KB
    __shared__ float As[8][F_IN];        // 2 KB
    int tx = threadIdx.x, ty = threadIdx.y;
    int tid = ty * 32 + tx;
    for (int i = tid; i < F_IN * F_MID; i += 256) Ws[i] = W1[i];
    int row0 = blockIdx.x * 8;
    for (int i = tid; i < 8 * F_IN; i += 256) {
        int r = row0 + (i >> 6);
        As[i >> 6][i & 63] = (r < N_NODES) ? g_agg1[(size_t)r * F_IN + (i & 63)] : 0.f;
    }
    __syncthreads();
    int row = row0 + ty;
    if (row >= N_NODES) return;
    float acc0 = 0.f, acc1 = 0.f, acc2 = 0.f, acc3 = 0.f;
#pragma unroll
    for (int k = 0; k < F_IN; k++) {
        float a = As[ty][k];
        const float* w = Ws + k * F_MID + tx;
        acc0 = fmaf(a, w[0],  acc0);
        acc1 = fmaf(a, w[32], acc1);
        acc2 = fmaf(a, w[64], acc2);
        acc3 = fmaf(a, w[96], acc3);
    }
    float nd = g_norm_dst[row];
    float* o = g_h1 + (size_t)row * F_MID + tx;
    o[0]  = fmaxf(fmaf(acc0, nd, b1[tx]),      0.f);
    o[32] = fmaxf(fmaf(acc1, nd, b1[tx + 32]), 0.f);
    o[64] = fmaxf(fmaf(acc2, nd, b1[tx + 64]), 0.f);
    o[96] = fmaxf(fmaf(acc3, nd, b1[tx + 96]), 0.f);
}

// t2 = norm_src ⊙ (h1 @ W2)   — W2: [128,64] in smem, 8 rows/block, 2 cols/thread.
__global__ __launch_bounds__(256) void gemm2_kernel(const float* __restrict__ W2) {
    __shared__ float Ws[F_MID * F_IN];   // 32 KB
    __shared__ float As[8][F_MID];       // 4 KB
    int tx = threadIdx.x, ty = threadIdx.y;
    int tid = ty * 32 + tx;
    for (int i = tid; i < F_MID * F_IN; i += 256) Ws[i] = W2[i];
    int row0 = blockIdx.x * 8;
    for (int i = tid; i < 8 * F_MID; i += 256) {
        int r = row0 + (i >> 7);
        As[i >> 7][i & 127] = (r < N_NODES) ? g_h1[(size_t)r * F_MID + (i & 127)] : 0.f;
    }
    __syncthreads();
    int row = row0 + ty;
    if (row >= N_NODES) return;
    float acc0 = 0.f, acc1 = 0.f;
#pragma unroll
    for (int k = 0; k < F_MID; k++) {
        float a = As[ty][k];
        acc0 = fmaf(a, Ws[k * F_IN + tx],      acc0);
        acc1 = fmaf(a, Ws[k * F_IN + tx + 32], acc1);
    }
    float ns = g_norm_src[row];
    g_t2[(size_t)row * F_IN + tx]      = acc0 * ns;
    g_t2[(size_t)row * F_IN + tx + 32] = acc1 * ns;
}

// Layer-2 scatter: out[dst] += t2[src]
__global__ void scatter2_kernel(const int* __restrict__ src,
                                const int* __restrict__ dst,
                                float* __restrict__ out) {
    long long tid = (long long)blockIdx.x * blockDim.x + threadIdx.x;
    int e = (int)(tid >> 4);
    if (e >= N_EDGES) return;
    int c = ((int)tid & 15) << 2;
    int s = src[e], d = dst[e];
    float4 v = *reinterpret_cast<const float4*>(g_t2 + (size_t)s * F_IN + c);
    red_add_v4(out + (size_t)d * F_IN + c, v);
}

// out = out * norm_dst + b2
__global__ void epilogue_kernel(const float* __restrict__ b2,
                                float* __restrict__ out) {
    int i = blockIdx.x * blockDim.x + threadIdx.x;
    if (i >= N_NODES * F_IN) return;
    int row = i >> 6;
    int col = i & 63;
    out[i] = fmaf(out[i], g_norm_dst[row], b2[col]);
}

// ---------------- launch ----------------
extern "C" void kernel_launch(void* const* d_in, const int* in_sizes, int n_in,
                              void* d_out, int out_size) {
    const float* h   = (const float*)d_in[0];
    const int*   src = (const int*)  d_in[1];
    const int*   dst = (const int*)  d_in[2];
    const float* W1  = (const float*)d_in[3];
    const float* b1  = (const float*)d_in[4];
    const float* W2  = (const float*)d_in[5];
    const float* b2  = (const float*)d_in[6];
    float* out = (float*)d_out;

    const int NF = N_NODES * F_IN;                 // 3.2M
    zero_kernel<<<(NF + 255) / 256, 256>>>(out);
    degree_kernel<<<(N_EDGES + 255) / 256, 256>>>(src, dst);
    norm_kernel<<<(N_NODES + 255) / 256, 256>>>();

    const long long s_threads = (long long)N_EDGES * 16;
    scatter1_kernel<<<(unsigned)((s_threads + 255) / 256), 256>>>(h, src, dst);

    dim3 gblk(32, 8);
    gemm1_kernel<<<(N_NODES + 7) / 8, gblk>>>(W1, b1);
    gemm2_kernel<<<(N_NODES + 7) / 8, gblk>>>(W2);

    scatter2_kernel<<<(unsigned)((s_threads + 255) / 256), 256>>>(src, dst, out);
    epilogue_kernel<<<(NF + 255) / 256, 256>>>(b2, out);
}

// round 4
// speedup vs baseline: 1.3076x; 1.3076x over previous
#include <cuda_runtime.h>
#include <cuda_bf16.h>
#include <cstdint>

#define N_NODES 50000
#define N_EDGES 800000
#define F_IN    64
#define F_MID   128

// ---------------- scratch (device globals; no allocations) ----------------
__device__ int   g_deg_out[N_NODES];
__device__ int   g_deg_in [N_NODES];
__device__ float g_norm_src[N_NODES];
__device__ float g_norm_dst[N_NODES];
__device__ float g_agg1[(size_t)N_NODES * F_IN];    // 12.8 MB
__device__ float g_h1  [(size_t)N_NODES * F_MID];   // 25.6 MB
__device__ float g_t2  [(size_t)N_NODES * F_IN];    // 12.8 MB

// ---------------- helpers ----------------
__device__ __forceinline__ void red_add_v4(float* p, float4 v) {
    asm volatile("red.global.add.v4.f32 [%0], {%1,%2,%3,%4};"
                 :: "l"(p), "f"(v.x), "f"(v.y), "f"(v.z), "f"(v.w)
                 : "memory");
}

// ---------------- kernels ----------------

// Zero degrees, agg1, and d_out (used as the layer-2 accumulator). float4 stores.
__global__ void zero_kernel(float* __restrict__ out) {
    int i = blockIdx.x * blockDim.x + threadIdx.x;   // 0 .. N_NODES*F_IN/4-1
    const int NF4 = N_NODES * F_IN / 4;
    if (i < NF4) {
        float4 z = make_float4(0.f, 0.f, 0.f, 0.f);
        reinterpret_cast<float4*>(g_agg1)[i] = z;
        reinterpret_cast<float4*>(out)[i]    = z;
    }
    if (i < N_NODES) {
        g_deg_out[i] = 0;
        g_deg_in[i]  = 0;
    }
}

__global__ void degree_kernel(const int* __restrict__ src,
                              const int* __restrict__ dst) {
    int e = blockIdx.x * blockDim.x + threadIdx.x;
    if (e >= N_EDGES) return;
    atomicAdd(&g_deg_out[src[e]], 1);
    atomicAdd(&g_deg_in [dst[e]], 1);
}

__global__ void norm_kernel() {
    int i = blockIdx.x * blockDim.x + threadIdx.x;
    if (i >= N_NODES) return;
    g_norm_src[i] = rsqrtf(fmaxf((float)g_deg_out[i], 1.f));
    g_norm_dst[i] = rsqrtf(fmaxf((float)g_deg_in [i], 1.f));
}

// Layer-1 scatter: agg1[dst] += h[src] * norm_src[src].
// 8 lanes/edge; each thread handles 8 consecutive floats (2x float4) -> MLP=2.
__global__ void scatter1_kernel(const float* __restrict__ h,
                                const int* __restrict__ src,
                                const int* __restrict__ dst) {
    int tid = blockIdx.x * blockDim.x + threadIdx.x;
    int e = tid >> 3;
    if (e >= N_EDGES) return;
    int c = (tid & 7) << 3;
    int s = src[e], d = dst[e];
    float ns = g_norm_src[s];
    const float4* p = reinterpret_cast<const float4*>(h + (size_t)s * F_IN + c);
    float4 v0 = p[0];
    float4 v1 = p[1];
    v0.x *= ns; v0.y *= ns; v0.z *= ns; v0.w *= ns;
    v1.x *= ns; v1.y *= ns; v1.z *= ns; v1.w *= ns;
    float* q = g_agg1 + (size_t)d * F_IN + c;
    red_add_v4(q, v0);
    red_add_v4(q + 4, v1);
}

// h1 = relu(norm_dst ⊙ (agg1 @ W1) + b1)
// Block: 32 rows x 128 cols, 256 threads, thread tile 4x4 (float4 rows & cols).
__global__ __launch_bounds__(256) void gemm1_kernel(const float* __restrict__ W1,
                                                    const float* __restrict__ b1) {
    __shared__ __align__(16) float Ws[F_IN * F_MID];   // [k][col], 32 KB
    __shared__ __align__(16) float As[F_IN][36];       // transposed: [k][row], 32 rows, pad 36
    int t  = threadIdx.x;
    int ct = t & 31;    // cols ct*4 .. ct*4+3
    int rt = t >> 5;    // rows rt*4 .. rt*4+3 (8 groups x 4 = 32 rows)
    int row0 = blockIdx.x * 32;

    // Load W1 (64x128), float4 coalesced
    for (int i = t; i < F_IN * F_MID / 4; i += 256)
        reinterpret_cast<float4*>(Ws)[i] = reinterpret_cast<const float4*>(W1)[i];

    // Load A tile 32x64 transposed into As[k][row]
    for (int i = t; i < 32 * F_IN / 4; i += 256) {
        int r  = i >> 4;        // 16 float4 per row
        int c4 = (i & 15) << 2;
        int row = row0 + r;
        float4 v = (row < N_NODES)
            ? *reinterpret_cast<const float4*>(g_agg1 + (size_t)row * F_IN + c4)
            : make_float4(0.f, 0.f, 0.f, 0.f);
        As[c4 + 0][r] = v.x; As[c4 + 1][r] = v.y;
        As[c4 + 2][r] = v.z; As[c4 + 3][r] = v.w;
    }
    __syncthreads();

    float4 acc0 = make_float4(0.f,0.f,0.f,0.f);
    float4 acc1 = acc0, acc2 = acc0, acc3 = acc0;
#pragma unroll 16
    for (int k = 0; k < F_IN; k++) {
        float4 w = *reinterpret_cast<const float4*>(&Ws[k * F_MID + (ct << 2)]);
        float4 a = *reinterpret_cast<const float4*>(&As[k][rt << 2]);
        acc0.x = fmaf(a.x, w.x, acc0.x); acc0.y = fmaf(a.x, w.y, acc0.y);
        acc0.z = fmaf(a.x, w.z, acc0.z); acc0.w = fmaf(a.x, w.w, acc0.w);
        acc1.x = fmaf(a.y, w.x, acc1.x); acc1.y = fmaf(a.y, w.y, acc1.y);
        acc1.z = fmaf(a.y, w.z, acc1.z); acc1.w = fmaf(a.y, w.w, acc1.w);
        acc2.x = fmaf(a.z, w.x, acc2.x); acc2.y = fmaf(a.z, w.y, acc2.y);
        acc2.z = fmaf(a.z, w.z, acc2.z); acc2.w = fmaf(a.z, w.w, acc2.w);
        acc3.x = fmaf(a.w, w.x, acc3.x); acc3.y = fmaf(a.w, w.y, acc3.y);
        acc3.z = fmaf(a.w, w.z, acc3.z); acc3.w = fmaf(a.w, w.w, acc3.w);
    }

    float4 bb = *reinterpret_cast<const float4*>(b1 + (ct << 2));
    float4 accs[4] = {acc0, acc1, acc2, acc3};
#pragma unroll
    for (int r = 0; r < 4; r++) {
        int row = row0 + (rt << 2) + r;
        if (row >= N_NODES) break;
        float nd = g_norm_dst[row];
        float4 o;
        o.x = fmaxf(fmaf(accs[r].x, nd, bb.x), 0.f);
        o.y = fmaxf(fmaf(accs[r].y, nd, bb.y), 0.f);
        o.z = fmaxf(fmaf(accs[r].z, nd, bb.z), 0.f);
        o.w = fmaxf(fmaf(accs[r].w, nd, bb.w), 0.f);
        *reinterpret_cast<float4*>(g_h1 + (size_t)row * F_MID + (ct << 2)) = o;
    }
}

// t2 = norm_src ⊙ (h1 @ W2)
// Block: 64 rows x 64 cols, 256 threads, thread tile 4x4.
__global__ __launch_bounds__(256) void gemm2_kernel(const float* __restrict__ W2) {
    __shared__ __align__(16) float Ws[F_MID * F_IN];   // [k][col], 32 KB
    __shared__ __align__(16) float As[F_MID][68];      // transposed: [k][row], 64 rows, pad 68
    int t  = threadIdx.x;
    int ct = t & 15;    // cols ct*4 (16 groups x 4 = 64 cols)
    int rt = t >> 4;    // rows rt*4 (16 groups x 4 = 64 rows)
    int row0 = blockIdx.x * 64;

    for (int i = t; i < F_MID * F_IN / 4; i += 256)
        reinterpret_cast<float4*>(Ws)[i] = reinterpret_cast<const float4*>(W2)[i];

    // Load A tile 64x128 transposed
    for (int i = t; i < 64 * F_MID / 4; i += 256) {
        int r  = i >> 5;        // 32 float4 per row
        int c4 = (i & 31) << 2;
        int row = row0 + r;
        float4 v = (row < N_NODES)
            ? *reinterpret_cast<const float4*>(g_h1 + (size_t)row * F_MID + c4)
            : make_float4(0.f, 0.f, 0.f, 0.f);
        As[c4 + 0][r] = v.x; As[c4 + 1][r] = v.y;
        As[c4 + 2][r] = v.z; As[c4 + 3][r] = v.w;
    }
    __syncthreads();

    float4 acc0 = make_float4(0.f,0.f,0.f,0.f);
    float4 acc1 = acc0, acc2 = acc0, acc3 = acc0;
#pragma unroll 8
    for (int k = 0; k < F_MID; k++) {
        float4 w = *reinterpret_cast<const float4*>(&Ws[k * F_IN + (ct << 2)]);
        float4 a = *reinterpret_cast<const float4*>(&As[k][rt << 2]);
        acc0.x = fmaf(a.x, w.x, acc0.x); acc0.y = fmaf(a.x, w.y, acc0.y);
        acc0.z = fmaf(a.x, w.z, acc0.z); acc0.w = fmaf(a.x, w.w, acc0.w);
        acc1.x = fmaf(a.y, w.x, acc1.x); acc1.y = fmaf(a.y, w.y, acc1.y);
        acc1.z = fmaf(a.y, w.z, acc1.z); acc1.w = fmaf(a.y, w.w, acc1.w);
        acc2.x = fmaf(a.z, w.x, acc2.x); acc2.y = fmaf(a.z, w.y, acc2.y);
        acc2.z = fmaf(a.z, w.z, acc2.z); acc2.w = fmaf(a.z, w.w, acc2.w);
        acc3.x = fmaf(a.w, w.x, acc3.x); acc3.y = fmaf(a.w, w.y, acc3.y);
        acc3.z = fmaf(a.w, w.z, acc3.z); acc3.w = fmaf(a.w, w.w, acc3.w);
    }

    float4 accs[4] = {acc0, acc1, acc2, acc3};
#pragma unroll
    for (int r = 0; r < 4; r++) {
        int row = row0 + (rt << 2) + r;
        if (row >= N_NODES) break;
        float ns = g_norm_src[row];
        float4 o;
        o.x = accs[r].x * ns; o.y = accs[r].y * ns;
        o.z = accs[r].z * ns; o.w = accs[r].w * ns;
        *reinterpret_cast<float4*>(g_t2 + (size_t)row * F_IN + (ct << 2)) = o;
    }
}

// Layer-2 scatter: out[dst] += t2[src].  8 lanes/edge, 2x float4/thread.
__global__ void scatter2_kernel(const int* __restrict__ src,
                                const int* __restrict__ dst,
                                float* __restrict__ out) {
    int tid = blockIdx.x * blockDim.x + threadIdx.x;
    int e = tid >> 3;
    if (e >= N_EDGES) return;
    int c = (tid & 7) << 3;
    int s = src[e], d = dst[e];
    const float4* p = reinterpret_cast<const float4*>(g_t2 + (size_t)s * F_IN + c);
    float4 v0 = p[0];
    float4 v1 = p[1];
    float* q = out + (size_t)d * F_IN + c;
    red_add_v4(q, v0);
    red_add_v4(q + 4, v1);
}

// out = out * norm_dst + b2   (float4)
__global__ void epilogue_kernel(const float* __restrict__ b2,
                                float* __restrict__ out) {
    int i = blockIdx.x * blockDim.x + threadIdx.x;
    const int NF4 = N_NODES * F_IN / 4;
    if (i >= NF4) return;
    int row = i >> 4;            // 16 float4 per row
    int c4  = (i & 15) << 2;
    float nd = g_norm_dst[row];
    float4 b = *reinterpret_cast<const float4*>(b2 + c4);
    float4 v = reinterpret_cast<float4*>(out)[i];
    v.x = fmaf(v.x, nd, b.x); v.y = fmaf(v.y, nd, b.y);
    v.z = fmaf(v.z, nd, b.z); v.w = fmaf(v.w, nd, b.w);
    reinterpret_cast<float4*>(out)[i] = v;
}

// ---------------- launch ----------------
extern "C" void kernel_launch(void* const* d_in, const int* in_sizes, int n_in,
                              void* d_out, int out_size) {
    const float* h   = (const float*)d_in[0];
    const int*   src = (const int*)  d_in[1];
    const int*   dst = (const int*)  d_in[2];
    const float* W1  = (const float*)d_in[3];
    const float* b1  = (const float*)d_in[4];
    const float* W2  = (const float*)d_in[5];
    const float* b2  = (const float*)d_in[6];
    float* out = (float*)d_out;

    const int NF4 = N_NODES * F_IN / 4;            // 800k
    zero_kernel<<<(NF4 + 255) / 256, 256>>>(out);
    degree_kernel<<<(N_EDGES + 255) / 256, 256>>>(src, dst);
    norm_kernel<<<(N_NODES + 255) / 256, 256>>>();

    const int s_threads = N_EDGES * 8;             // 6.4M
    scatter1_kernel<<<s_threads / 256, 256>>>(h, src, dst);

    gemm1_kernel<<<(N_NODES + 31) / 32, 256>>>(W1, b1);
    gemm2_kernel<<<(N_NODES + 63) / 64, 256>>>(W2);

    scatter2_kernel<<<s_threads / 256, 256>>>(src, dst, out);
    epilogue_kernel<<<(NF4 + 255) / 256, 256>>>(b2, out);
}

// round 5
// speedup vs baseline: 1.7990x; 1.3759x over previous
#include <cuda_runtime.h>
#include <cuda_bf16.h>
#include <cstdint>

#define N_NODES 50000
#define N_EDGES 800000
#define F_IN    64
#define F_MID   128

// ---------------- scratch (device globals; no allocations) ----------------
__device__ int   g_deg_out[N_NODES];
__device__ int   g_deg_in [N_NODES];
__device__ float g_norm_src[N_NODES];
__device__ float g_norm_dst[N_NODES];
__device__ int   g_off   [N_NODES];
__device__ int   g_cursor[N_NODES];
__device__ int   g_alloc;
__device__ int   g_esrc[N_EDGES];                   // src ids bucketed by dst
__device__ float g_hs  [(size_t)N_NODES * F_IN];    // h * norm_src
__device__ float g_agg1[(size_t)N_NODES * F_IN];
__device__ float g_h1  [(size_t)N_NODES * F_MID];
__device__ float g_t2  [(size_t)N_NODES * F_IN];

// ---------------- kernels ----------------

__global__ void zero_kernel() {
    int i = blockIdx.x * blockDim.x + threadIdx.x;
    if (i < N_NODES) { g_deg_out[i] = 0; g_deg_in[i] = 0; }
    if (i == 0) g_alloc = 0;
}

__global__ void degree_kernel(const int* __restrict__ src,
                              const int* __restrict__ dst) {
    int e = blockIdx.x * blockDim.x + threadIdx.x;
    if (e >= N_EDGES) return;
    atomicAdd(&g_deg_out[src[e]], 1);
    atomicAdd(&g_deg_in [dst[e]], 1);
}

// Per-block smem scan of deg_in + single atomic per block for CSR bucket offsets.
// Also computes both norms.
__global__ __launch_bounds__(256) void norm_offset_kernel() {
    __shared__ int s[256];
    __shared__ int base;
    int t = threadIdx.x;
    int i = blockIdx.x * 256 + t;
    int deg = 0, dout = 0;
    if (i < N_NODES) { deg = g_deg_in[i]; dout = g_deg_out[i]; }
    s[t] = deg;
    __syncthreads();
#pragma unroll
    for (int o = 1; o < 256; o <<= 1) {
        int v = (t >= o) ? s[t - o] : 0;
        __syncthreads();
        s[t] += v;
        __syncthreads();
    }
    if (t == 255) base = atomicAdd(&g_alloc, s[255]);
    __syncthreads();
    if (i < N_NODES) {
        int off = base + s[t] - deg;     // exclusive scan + block base
        g_off[i]    = off;
        g_cursor[i] = off;
        g_norm_src[i] = rsqrtf(fmaxf((float)dout, 1.f));
        g_norm_dst[i] = rsqrtf(fmaxf((float)deg,  1.f));
    }
}

__global__ void fill_kernel(const int* __restrict__ src,
                            const int* __restrict__ dst) {
    int e = blockIdx.x * blockDim.x + threadIdx.x;
    if (e >= N_EDGES) return;
    int pos = atomicAdd(&g_cursor[dst[e]], 1);
    g_esrc[pos] = src[e];
}

// hs = h * norm_src   (float4)
__global__ void prescale_kernel(const float* __restrict__ h) {
    int i = blockIdx.x * blockDim.x + threadIdx.x;
    const int NF4 = N_NODES * F_IN / 4;
    if (i >= NF4) return;
    float ns = g_norm_src[i >> 4];
    float4 v = reinterpret_cast<const float4*>(h)[i];
    v.x *= ns; v.y *= ns; v.z *= ns; v.w *= ns;
    reinterpret_cast<float4*>(g_hs)[i] = v;
}

// Pull-aggregation layer 1: agg1[n] = sum over incoming edges of hs[src].
// 8 threads per node, each owns 8 floats (2x float4 accumulators).
__global__ void aggregate1_kernel() {
    int tid = blockIdx.x * blockDim.x + threadIdx.x;
    int n = tid >> 3;
    if (n >= N_NODES) return;
    int c2 = (tid & 7) << 1;            // float4 index within row (0,2,...,14)
    int beg = g_off[n];
    int cnt = g_deg_in[n];
    const float4* hs4 = reinterpret_cast<const float4*>(g_hs);
    float4 a0 = make_float4(0.f,0.f,0.f,0.f);
    float4 a1 = a0;
#pragma unroll 4
    for (int i = 0; i < cnt; i++) {
        int s = g_esrc[beg + i];
        const float4* p = hs4 + (size_t)s * 16 + c2;
        float4 v0 = p[0], v1 = p[1];
        a0.x += v0.x; a0.y += v0.y; a0.z += v0.z; a0.w += v0.w;
        a1.x += v1.x; a1.y += v1.y; a1.z += v1.z; a1.w += v1.w;
    }
    float4* o = reinterpret_cast<float4*>(g_agg1) + (size_t)n * 16 + c2;
    o[0] = a0; o[1] = a1;
}

// h1 = relu(norm_dst ⊙ (agg1 @ W1) + b1)
// Block: 64 rows x 128 cols, 256 threads, thread tile 8x4.
__global__ __launch_bounds__(256) void gemm1_kernel(const float* __restrict__ W1,
                                                    const float* __restrict__ b1) {
    __shared__ __align__(16) float Ws[F_IN * F_MID];   // [k][col], 32 KB
    __shared__ __align__(16) float As[F_IN][68];       // transposed: [k][row], 64 rows
    int t  = threadIdx.x;
    int ct = t & 31;    // cols ct*4
    int rt = t >> 5;    // rows rt*8 .. rt*8+7
    int row0 = blockIdx.x * 64;

    for (int i = t; i < F_IN * F_MID / 4; i += 256)
        reinterpret_cast<float4*>(Ws)[i] = reinterpret_cast<const float4*>(W1)[i];

    for (int i = t; i < 64 * F_IN / 4; i += 256) {
        int r  = i >> 4;
        int c4 = (i & 15) << 2;
        int row = row0 + r;
        float4 v = (row < N_NODES)
            ? *reinterpret_cast<const float4*>(g_agg1 + (size_t)row * F_IN + c4)
            : make_float4(0.f, 0.f, 0.f, 0.f);
        As[c4 + 0][r] = v.x; As[c4 + 1][r] = v.y;
        As[c4 + 2][r] = v.z; As[c4 + 3][r] = v.w;
    }
    __syncthreads();

    float4 acc[8];
#pragma unroll
    for (int j = 0; j < 8; j++) acc[j] = make_float4(0.f,0.f,0.f,0.f);

#pragma unroll 8
    for (int k = 0; k < F_IN; k++) {
        float4 w  = *reinterpret_cast<const float4*>(&Ws[k * F_MID + (ct << 2)]);
        float4 aA = *reinterpret_cast<const float4*>(&As[k][rt << 3]);
        float4 aB = *reinterpret_cast<const float4*>(&As[k][(rt << 3) + 4]);
        acc[0].x = fmaf(aA.x, w.x, acc[0].x); acc[0].y = fmaf(aA.x, w.y, acc[0].y);
        acc[0].z = fmaf(aA.x, w.z, acc[0].z); acc[0].w = fmaf(aA.x, w.w, acc[0].w);
        acc[1].x = fmaf(aA.y, w.x, acc[1].x); acc[1].y = fmaf(aA.y, w.y, acc[1].y);
        acc[1].z = fmaf(aA.y, w.z, acc[1].z); acc[1].w = fmaf(aA.y, w.w, acc[1].w);
        acc[2].x = fmaf(aA.z, w.x, acc[2].x); acc[2].y = fmaf(aA.z, w.y, acc[2].y);
        acc[2].z = fmaf(aA.z, w.z, acc[2].z); acc[2].w = fmaf(aA.z, w.w, acc[2].w);
        acc[3].x = fmaf(aA.w, w.x, acc[3].x); acc[3].y = fmaf(aA.w, w.y, acc[3].y);
        acc[3].z = fmaf(aA.w, w.z, acc[3].z); acc[3].w = fmaf(aA.w, w.w, acc[3].w);
        acc[4].x = fmaf(aB.x, w.x, acc[4].x); acc[4].y = fmaf(aB.x, w.y, acc[4].y);
        acc[4].z = fmaf(aB.x, w.z, acc[4].z); acc[4].w = fmaf(aB.x, w.w, acc[4].w);
        acc[5].x = fmaf(aB.y, w.x, acc[5].x); acc[5].y = fmaf(aB.y, w.y, acc[5].y);
        acc[5].z = fmaf(aB.y, w.z, acc[5].z); acc[5].w = fmaf(aB.y, w.w, acc[5].w);
        acc[6].x = fmaf(aB.z, w.x, acc[6].x); acc[6].y = fmaf(aB.z, w.y, acc[6].y);
        acc[6].z = fmaf(aB.z, w.z, acc[6].z); acc[6].w = fmaf(aB.z, w.w, acc[6].w);
        acc[7].x = fmaf(aB.w, w.x, acc[7].x); acc[7].y = fmaf(aB.w, w.y, acc[7].y);
        acc[7].z = fmaf(aB.w, w.z, acc[7].z); acc[7].w = fmaf(aB.w, w.w, acc[7].w);
    }

    float4 bb = *reinterpret_cast<const float4*>(b1 + (ct << 2));
#pragma unroll
    for (int j = 0; j < 8; j++) {
        int row = row0 + (rt << 3) + j;
        if (row >= N_NODES) break;
        float nd = g_norm_dst[row];
        float4 o;
        o.x = fmaxf(fmaf(acc[j].x, nd, bb.x), 0.f);
        o.y = fmaxf(fmaf(acc[j].y, nd, bb.y), 0.f);
        o.z = fmaxf(fmaf(acc[j].z, nd, bb.z), 0.f);
        o.w = fmaxf(fmaf(acc[j].w, nd, bb.w), 0.f);
        *reinterpret_cast<float4*>(g_h1 + (size_t)row * F_MID + (ct << 2)) = o;
    }
}

// t2 = norm_src ⊙ (h1 @ W2)   — 64 rows x 64 cols / block, 4x4 tile.
__global__ __launch_bounds__(256) void gemm2_kernel(const float* __restrict__ W2) {
    __shared__ __align__(16) float Ws[F_MID * F_IN];   // 32 KB
    __shared__ __align__(16) float As[F_MID][68];
    int t  = threadIdx.x;
    int ct = t & 15;
    int rt = t >> 4;
    int row0 = blockIdx.x * 64;

    for (int i = t; i < F_MID * F_IN / 4; i += 256)
        reinterpret_cast<float4*>(Ws)[i] = reinterpret_cast<const float4*>(W2)[i];

    for (int i = t; i < 64 * F_MID / 4; i += 256) {
        int r  = i >> 5;
        int c4 = (i & 31) << 2;
        int row = row0 + r;
        float4 v = (row < N_NODES)
            ? *reinterpret_cast<const float4*>(g_h1 + (size_t)row * F_MID + c4)
            : make_float4(0.f, 0.f, 0.f, 0.f);
        As[c4 + 0][r] = v.x; As[c4 + 1][r] = v.y;
        As[c4 + 2][r] = v.z; As[c4 + 3][r] = v.w;
    }
    __syncthreads();

    float4 acc0 = make_float4(0.f,0.f,0.f,0.f);
    float4 acc1 = acc0, acc2 = acc0, acc3 = acc0;
#pragma unroll 8
    for (int k = 0; k < F_MID; k++) {
        float4 w = *reinterpret_cast<const float4*>(&Ws[k * F_IN + (ct << 2)]);
        float4 a = *reinterpret_cast<const float4*>(&As[k][rt << 2]);
        acc0.x = fmaf(a.x, w.x, acc0.x); acc0.y = fmaf(a.x, w.y, acc0.y);
        acc0.z = fmaf(a.x, w.z, acc0.z); acc0.w = fmaf(a.x, w.w, acc0.w);
        acc1.x = fmaf(a.y, w.x, acc1.x); acc1.y = fmaf(a.y, w.y, acc1.y);
        acc1.z = fmaf(a.y, w.z, acc1.z); acc1.w = fmaf(a.y, w.w, acc1.w);
        acc2.x = fmaf(a.z, w.x, acc2.x); acc2.y = fmaf(a.z, w.y, acc2.y);
        acc2.z = fmaf(a.z, w.z, acc2.z); acc2.w = fmaf(a.z, w.w, acc2.w);
        acc3.x = fmaf(a.w, w.x, acc3.x); acc3.y = fmaf(a.w, w.y, acc3.y);
        acc3.z = fmaf(a.w, w.z, acc3.z); acc3.w = fmaf(a.w, w.w, acc3.w);
    }

    float4 accs[4] = {acc0, acc1, acc2, acc3};
#pragma unroll
    for (int r = 0; r < 4; r++) {
        int row = row0 + (rt << 2) + r;
        if (row >= N_NODES) break;
        float ns = g_norm_src[row];
        float4 o;
        o.x = accs[r].x * ns; o.y = accs[r].y * ns;
        o.z = accs[r].z * ns; o.w = accs[r].w * ns;
        *reinterpret_cast<float4*>(g_t2 + (size_t)row * F_IN + (ct << 2)) = o;
    }
}

// Pull-aggregation layer 2 + fused epilogue: out[n] = (sum t2[src]) * norm_dst[n] + b2
__global__ void aggregate2_kernel(const float* __restrict__ b2,
                                  float* __restrict__ out) {
    int tid = blockIdx.x * blockDim.x + threadIdx.x;
    int n = tid >> 3;
    if (n >= N_NODES) return;
    int c2 = (tid & 7) << 1;
    int beg = g_off[n];
    int cnt = g_deg_in[n];
    const float4* t4 = reinterpret_cast<const float4*>(g_t2);
    float4 a0 = make_float4(0.f,0.f,0.f,0.f);
    float4 a1 = a0;
#pragma unroll 4
    for (int i = 0; i < cnt; i++) {
        int s = g_esrc[beg + i];
        const float4* p = t4 + (size_t)s * 16 + c2;
        float4 v0 = p[0], v1 = p[1];
        a0.x += v0.x; a0.y += v0.y; a0.z += v0.z; a0.w += v0.w;
        a1.x += v1.x; a1.y += v1.y; a1.z += v1.z; a1.w += v1.w;
    }
    float nd = g_norm_dst[n];
    float4 b0 = reinterpret_cast<const float4*>(b2)[c2];
    float4 b1v = reinterpret_cast<const float4*>(b2)[c2 + 1];
    float4 o0, o1;
    o0.x = fmaf(a0.x, nd, b0.x);  o0.y = fmaf(a0.y, nd, b0.y);
    o0.z = fmaf(a0.z, nd, b0.z);  o0.w = fmaf(a0.w, nd, b0.w);
    o1.x = fmaf(a1.x, nd, b1v.x); o1.y = fmaf(a1.y, nd, b1v.y);
    o1.z = fmaf(a1.z, nd, b1v.z); o1.w = fmaf(a1.w, nd, b1v.w);
    float4* o = reinterpret_cast<float4*>(out) + (size_t)n * 16 + c2;
    o[0] = o0; o[1] = o1;
}

// ---------------- launch ----------------
extern "C" void kernel_launch(void* const* d_in, const int* in_sizes, int n_in,
                              void* d_out, int out_size) {
    const float* h   = (const float*)d_in[0];
    const int*   src = (const int*)  d_in[1];
    const int*   dst = (const int*)  d_in[2];
    const float* W1  = (const float*)d_in[3];
    const float* b1  = (const float*)d_in[4];
    const float* W2  = (const float*)d_in[5];
    const float* b2  = (const float*)d_in[6];
    float* out = (float*)d_out;

    zero_kernel<<<(N_NODES + 255) / 256, 256>>>();
    degree_kernel<<<(N_EDGES + 255) / 256, 256>>>(src, dst);
    norm_offset_kernel<<<(N_NODES + 255) / 256, 256>>>();
    fill_kernel<<<(N_EDGES + 255) / 256, 256>>>(src, dst);

    const int NF4 = N_NODES * F_IN / 4;
    prescale_kernel<<<(NF4 + 255) / 256, 256>>>(h);

    const int a_threads = N_NODES * 8;
    aggregate1_kernel<<<(a_threads + 255) / 256, 256>>>();

    gemm1_kernel<<<(N_NODES + 63) / 64, 256>>>(W1, b1);
    gemm2_kernel<<<(N_NODES + 63) / 64, 256>>>(W2);

    aggregate2_kernel<<<(a_threads + 255) / 256, 256>>>(b2, out);
}

// round 7
// speedup vs baseline: 1.8443x; 1.0252x over previous
#include <cuda_runtime.h>
#include <cuda_bf16.h>
#include <cstdint>

#define N_NODES 50000
#define N_EDGES 800000
#define F_IN    64
#define F_MID   128

// ---------------- scratch (device globals; no allocations) ----------------
__device__ int   g_deg_out[N_NODES];
__device__ int   g_deg_in [N_NODES];
__device__ float g_norm_src[N_NODES];
__device__ float g_norm_dst[N_NODES];
__device__ int   g_off [N_NODES];
__device__ int   g_alloc;
__device__ int   g_rank[N_EDGES];                   // rank of edge within its dst bucket
__device__ int   g_esrc[N_EDGES];                   // src ids bucketed by dst
__device__ float g_hs  [(size_t)N_NODES * F_IN];    // h * norm_src
__device__ float g_agg1[(size_t)N_NODES * F_IN];
__device__ float g_h1  [(size_t)N_NODES * F_MID];
__device__ float g_t2  [(size_t)N_NODES * F_IN];

// ---------------- kernels ----------------

__global__ void zero_kernel() {
    int i = blockIdx.x * blockDim.x + threadIdx.x;
    if (i < N_NODES) { g_deg_out[i] = 0; g_deg_in[i] = 0; }
    if (i == 0) g_alloc = 0;
}

// Degrees; the in-degree atomic's return value is this edge's bucket rank (free).
__global__ void degree_kernel(const int* __restrict__ src,
                              const int* __restrict__ dst) {
    int e = blockIdx.x * blockDim.x + threadIdx.x;
    if (e >= N_EDGES) return;
    atomicAdd(&g_deg_out[src[e]], 1);
    g_rank[e] = atomicAdd(&g_deg_in[dst[e]], 1);
}

// Per-block smem scan of deg_in + single atomic per block for CSR bucket offsets.
// Also computes both norms.
__global__ __launch_bounds__(256) void norm_offset_kernel() {
    __shared__ int s[256];
    __shared__ int base;
    int t = threadIdx.x;
    int i = blockIdx.x * 256 + t;
    int deg = 0, dout = 0;
    if (i < N_NODES) { deg = g_deg_in[i]; dout = g_deg_out[i]; }
    s[t] = deg;
    __syncthreads();
#pragma unroll
    for (int o = 1; o < 256; o <<= 1) {
        int v = (t >= o) ? s[t - o] : 0;
        __syncthreads();
        s[t] += v;
        __syncthreads();
    }
    if (t == 255) base = atomicAdd(&g_alloc, s[255]);
    __syncthreads();
    if (i < N_NODES) {
        g_off[i] = base + s[t] - deg;     // exclusive scan + block base
        g_norm_src[i] = rsqrtf(fmaxf((float)dout, 1.f));
        g_norm_dst[i] = rsqrtf(fmaxf((float)deg,  1.f));
    }
}

// Atomic-free CSR fill using the precomputed rank.
__global__ void fill_kernel(const int* __restrict__ src,
                            const int* __restrict__ dst) {
    int e = blockIdx.x * blockDim.x + threadIdx.x;
    if (e >= N_EDGES) return;
    g_esrc[__ldg(&g_off[dst[e]]) + g_rank[e]] = src[e];
}

// hs = h * norm_src   (float4)
__global__ void prescale_kernel(const float* __restrict__ h) {
    int i = blockIdx.x * blockDim.x + threadIdx.x;
    const int NF4 = N_NODES * F_IN / 4;
    if (i >= NF4) return;
    float ns = g_norm_src[i >> 4];
    float4 v = reinterpret_cast<const float4*>(h)[i];
    v.x *= ns; v.y *= ns; v.z *= ns; v.w *= ns;
    reinterpret_cast<float4*>(g_hs)[i] = v;
}

// Accumulate one source row chunk (2 float4) into (a0,a1).
__device__ __forceinline__ void acc_row(const float4* __restrict__ base4, int s, int c2,
                                        float4& a0, float4& a1) {
    const float4* p = base4 + (size_t)s * 16 + c2;
    float4 v0 = __ldg(p), v1 = __ldg(p + 1);
    a0.x += v0.x; a0.y += v0.y; a0.z += v0.z; a0.w += v0.w;
    a1.x += v1.x; a1.y += v1.y; a1.z += v1.z; a1.w += v1.w;
}

// Pull-aggregation layer 1: agg1[n] = sum over incoming edges of hs[src].
// 8 threads per node; int4-vectorized index stream (4 independent gathers in flight).
__global__ void aggregate1_kernel() {
    int tid = blockIdx.x * blockDim.x + threadIdx.x;
    int n = tid >> 3;
    if (n >= N_NODES) return;
    int c2 = (tid & 7) << 1;
    int i   = __ldg(&g_off[n]);
    int end = i + __ldg(&g_deg_in[n]);
    const float4* hs4 = reinterpret_cast<const float4*>(g_hs);
    float4 a0 = make_float4(0.f,0.f,0.f,0.f);
    float4 a1 = a0;
    while ((i & 3) && i < end) acc_row(hs4, __ldg(&g_esrc[i++]), c2, a0, a1);
    const int4* e4 = reinterpret_cast<const int4*>(g_esrc);
    for (; i + 4 <= end; i += 4) {
        int4 q = __ldg(&e4[i >> 2]);
        acc_row(hs4, q.x, c2, a0, a1);
        acc_row(hs4, q.y, c2, a0, a1);
        acc_row(hs4, q.z, c2, a0, a1);
        acc_row(hs4, q.w, c2, a0, a1);
    }
    for (; i < end; i++) acc_row(hs4, __ldg(&g_esrc[i]), c2, a0, a1);
    float4* o = reinterpret_cast<float4*>(g_agg1) + (size_t)n * 16 + c2;
    o[0] = a0; o[1] = a1;
}

// h1 = relu(norm_dst ⊙ (agg1 @ W1) + b1)
// Block: 64 rows x 128 cols, 256 threads, thread tile 8x4.
__global__ __launch_bounds__(256) void gemm1_kernel(const float* __restrict__ W1,
                                                    const float* __restrict__ b1) {
    __shared__ __align__(16) float Ws[F_IN * F_MID];   // [k][col], 32 KB
    __shared__ __align__(16) float As[F_IN][68];       // transposed: [k][row], 64 rows
    int t  = threadIdx.x;
    int ct = t & 31;
    int rt = t >> 5;
    int row0 = blockIdx.x * 64;

    for (int i = t; i < F_IN * F_MID / 4; i += 256)
        reinterpret_cast<float4*>(Ws)[i] = reinterpret_cast<const float4*>(W1)[i];

    for (int i = t; i < 64 * F_IN / 4; i += 256) {
        int r  = i >> 4;
        int c4 = (i & 15) << 2;
        int row = row0 + r;
        float4 v = (row < N_NODES)
            ? *reinterpret_cast<const float4*>(g_agg1 + (size_t)row * F_IN + c4)
            : make_float4(0.f, 0.f, 0.f, 0.f);
        As[c4 + 0][r] = v.x; As[c4 + 1][r] = v.y;
        As[c4 + 2][r] = v.z; As[c4 + 3][r] = v.w;
    }
    __syncthreads();

    float4 acc[8];
#pragma unroll
    for (int j = 0; j < 8; j++) acc[j] = make_float4(0.f,0.f,0.f,0.f);

#pragma unroll 8
    for (int k = 0; k < F_IN; k++) {
        float4 w  = *reinterpret_cast<const float4*>(&Ws[k * F_MID + (ct << 2)]);
        float4 aA = *reinterpret_cast<const float4*>(&As[k][rt << 3]);
        float4 aB = *reinterpret_cast<const float4*>(&As[k][(rt << 3) + 4]);
        acc[0].x = fmaf(aA.x, w.x, acc[0].x); acc[0].y = fmaf(aA.x, w.y, acc[0].y);
        acc[0].z = fmaf(aA.x, w.z, acc[0].z); acc[0].w = fmaf(aA.x, w.w, acc[0].w);
        acc[1].x = fmaf(aA.y, w.x, acc[1].x); acc[1].y = fmaf(aA.y, w.y, acc[1].y);
        acc[1].z = fmaf(aA.y, w.z, acc[1].z); acc[1].w = fmaf(aA.y, w.w, acc[1].w);
        acc[2].x = fmaf(aA.z, w.x, acc[2].x); acc[2].y = fmaf(aA.z, w.y, acc[2].y);
        acc[2].z = fmaf(aA.z, w.z, acc[2].z); acc[2].w = fmaf(aA.z, w.w, acc[2].w);
        acc[3].x = fmaf(aA.w, w.x, acc[3].x); acc[3].y = fmaf(aA.w, w.y, acc[3].y);
        acc[3].z = fmaf(aA.w, w.z, acc[3].z); acc[3].w = fmaf(aA.w, w.w, acc[3].w);
        acc[4].x = fmaf(aB.x, w.x, acc[4].x); acc[4].y = fmaf(aB.x, w.y, acc[4].y);
        acc[4].z = fmaf(aB.x, w.z, acc[4].z); acc[4].w = fmaf(aB.x, w.w, acc[4].w);
        acc[5].x = fmaf(aB.y, w.x, acc[5].x); acc[5].y = fmaf(aB.y, w.y, acc[5].y);
        acc[5].z = fmaf(aB.y, w.z, acc[5].z); acc[5].w = fmaf(aB.y, w.w, acc[5].w);
        acc[6].x = fmaf(aB.z, w.x, acc[6].x); acc[6].y = fmaf(aB.z, w.y, acc[6].y);
        acc[6].z = fmaf(aB.z, w.z, acc[6].z); acc[6].w = fmaf(aB.z, w.w, acc[6].w);
        acc[7].x = fmaf(aB.w, w.x, acc[7].x); acc[7].y = fmaf(aB.w, w.y, acc[7].y);
        acc[7].z = fmaf(aB.w, w.z, acc[7].z); acc[7].w = fmaf(aB.w, w.w, acc[7].w);
    }

    float4 bb = *reinterpret_cast<const float4*>(b1 + (ct << 2));
#pragma unroll
    for (int j = 0; j < 8; j++) {
        int row = row0 + (rt << 3) + j;
        if (row >= N_NODES) break;
        float nd = g_norm_dst[row];
        float4 o;
        o.x = fmaxf(fmaf(acc[j].x, nd, bb.x), 0.f);
        o.y = fmaxf(fmaf(acc[j].y, nd, bb.y), 0.f);
        o.z = fmaxf(fmaf(acc[j].z, nd, bb.z), 0.f);
        o.w = fmaxf(fmaf(acc[j].w, nd, bb.w), 0.f);
        *reinterpret_cast<float4*>(g_h1 + (size_t)row * F_MID + (ct << 2)) = o;
    }
}

// t2 = norm_src ⊙ (h1 @ W2)   — 64 rows x 64 cols / block, 4x4 tile.
__global__ __launch_bounds__(256) void gemm2_kernel(const float* __restrict__ W2) {
    __shared__ __align__(16) float Ws[F_MID * F_IN];   // 32 KB
    __shared__ __align__(16) float As[F_MID][68];
    int t  = threadIdx.x;
    int ct = t & 15;
    int rt = t >> 4;
    int row0 = blockIdx.x * 64;

    for (int i = t; i < F_MID * F_IN / 4; i += 256)
        reinterpret_cast<float4*>(Ws)[i] = reinterpret_cast<const float4*>(W2)[i];

    for (int i = t; i < 64 * F_MID / 4; i += 256) {
        int r  = i >> 5;
        int c4 = (i & 31) << 2;
        int row = row0 + r;
        float4 v = (row < N_NODES)
            ? *reinterpret_cast<const float4*>(g_h1 + (size_t)row * F_MID + c4)
            : make_float4(0.f, 0.f, 0.f, 0.f);
        As[c4 + 0][r] = v.x; As[c4 + 1][r] = v.y;
        As[c4 + 2][r] = v.z; As[c4 + 3][r] = v.w;
    }
    __syncthreads();

    float4 acc0 = make_float4(0.f,0.f,0.f,0.f);
    float4 acc1 = acc0, acc2 = acc0, acc3 = acc0;
#pragma unroll 8
    for (int k = 0; k < F_MID; k++) {
        float4 w = *reinterpret_cast<const float4*>(&Ws[k * F_IN + (ct << 2)]);
        float4 a = *reinterpret_cast<const float4*>(&As[k][rt << 2]);
        acc0.x = fmaf(a.x, w.x, acc0.x); acc0.y = fmaf(a.x, w.y, acc0.y);
        acc0.z = fmaf(a.x, w.z, acc0.z); acc0.w = fmaf(a.x, w.w, acc0.w);
        acc1.x = fmaf(a.y, w.x, acc1.x); acc1.y = fmaf(a.y, w.y, acc1.y);
        acc1.z = fmaf(a.y, w.z, acc1.z); acc1.w = fmaf(a.y, w.w, acc1.w);
        acc2.x = fmaf(a.z, w.x, acc2.x); acc2.y = fmaf(a.z, w.y, acc2.y);
        acc2.z = fmaf(a.z, w.z, acc2.z); acc2.w = fmaf(a.z, w.w, acc2.w);
        acc3.x = fmaf(a.w, w.x, acc3.x); acc3.y = fmaf(a.w, w.y, acc3.y);
        acc3.z = fmaf(a.w, w.z, acc3.z); acc3.w = fmaf(a.w, w.w, acc3.w);
    }

    float4 accs[4] = {acc0, acc1, acc2, acc3};
#pragma unroll
    for (int r = 0; r < 4; r++) {
        int row = row0 + (rt << 2) + r;
        if (row >= N_NODES) break;
        float ns = g_norm_src[row];
        float4 o;
        o.x = accs[r].x * ns; o.y = accs[r].y * ns;
        o.z = accs[r].z * ns; o.w = accs[r].w * ns;
        *reinterpret_cast<float4*>(g_t2 + (size_t)row * F_IN + (ct << 2)) = o;
    }
}

// Pull-aggregation layer 2 + fused epilogue: out[n] = (sum t2[src]) * norm_dst[n] + b2
__global__ void aggregate2_kernel(const float* __restrict__ b2,
                                  float* __restrict__ out) {
    int tid = blockIdx.x * blockDim.x + threadIdx.x;
    int n = tid >> 3;
    if (n >= N_NODES) return;
    int c2 = (tid & 7) << 1;
    int i   = __ldg(&g_off[n]);
    int end = i + __ldg(&g_deg_in[n]);
    const float4* t4 = reinterpret_cast<const float4*>(g_t2);
    float4 a0 = make_float4(0.f,0.f,0.f,0.f);
    float4 a1 = a0;
    while ((i & 3) && i < end) acc_row(t4, __ldg(&g_esrc[i++]), c2, a0, a1);
    const int4* e4 = reinterpret_cast<const int4*>(g_esrc);
    for (; i + 4 <= end; i += 4) {
        int4 q = __ldg(&e4[i >> 2]);
        acc_row(t4, q.x, c2, a0, a1);
        acc_row(t4, q.y, c2, a0, a1);
        acc_row(t4, q.z, c2, a0, a1);
        acc_row(t4, q.w, c2, a0, a1);
    }
    for (; i < end; i++) acc_row(t4, __ldg(&g_esrc[i]), c2, a0, a1);

    float nd = g_norm_dst[n];
    float4 b0 = reinterpret_cast<const float4*>(b2)[c2];
    float4 b1v = reinterpret_cast<const float4*>(b2)[c2 + 1];
    float4 o0, o1;
    o0.x = fmaf(a0.x, nd, b0.x);  o0.y = fmaf(a0.y, nd, b0.y);
    o0.z = fmaf(a0.z, nd, b0.z);  o0.w = fmaf(a0.w, nd, b0.w);
    o1.x = fmaf(a1.x, nd, b1v.x); o1.y = fmaf(a1.y, nd, b1v.y);
    o1.z = fmaf(a1.z, nd, b1v.z); o1.w = fmaf(a1.w, nd, b1v.w);
    float4* o = reinterpret_cast<float4*>(out) + (size_t)n * 16 + c2;
    o[0] = o0; o[1] = o1;
}

// ---------------- launch ----------------
extern "C" void kernel_launch(void* const* d_in, const int* in_sizes, int n_in,
                              void* d_out, int out_size) {
    const float* h   = (const float*)d_in[0];
    const int*   src = (const int*)  d_in[1];
    const int*   dst = (const int*)  d_in[2];
    const float* W1  = (const float*)d_in[3];
    const float* b1  = (const float*)d_in[4];
    const float* W2  = (const float*)d_in[5];
    const float* b2  = (const float*)d_in[6];
    float* out = (float*)d_out;

    zero_kernel<<<(N_NODES + 255) / 256, 256>>>();
    degree_kernel<<<(N_EDGES + 255) / 256, 256>>>(src, dst);
    norm_offset_kernel<<<(N_NODES + 255) / 256, 256>>>();
    fill_kernel<<<(N_EDGES + 255) / 256, 256>>>(src, dst);

    const int NF4 = N_NODES * F_IN / 4;
    prescale_kernel<<<(NF4 + 255) / 256, 256>>>(h);

    const int a_threads = N_NODES * 8;
    aggregate1_kernel<<<(a_threads + 255) / 256, 256>>>();

    gemm1_kernel<<<(N_NODES + 63) / 64, 256>>>(W1, b1);
    gemm2_kernel<<<(N_NODES + 63) / 64, 256>>>(W2);

    aggregate2_kernel<<<(a_threads + 255) / 256, 256>>>(b2, out);
}

// round 8
// speedup vs baseline: 1.8523x; 1.0044x over previous
#include <cuda_runtime.h>
#include <cuda_bf16.h>
#include <cstdint>

#define N_NODES 50000
#define N_EDGES 800000
#define F_IN    64
#define F_MID   128

// ---------------- scratch (device globals; no allocations) ----------------
__device__ int   g_deg_out[N_NODES];
__device__ int   g_deg_in [N_NODES];
__device__ float g_norm_src[N_NODES];
__device__ float g_norm_dst[N_NODES];
__device__ int   g_off [N_NODES];
__device__ int   g_alloc;
__device__ int   g_rank[N_EDGES];                   // rank of edge within its dst bucket
__device__ int   g_esrc[N_EDGES];                   // src ids bucketed by dst
__device__ float g_hs  [(size_t)N_NODES * F_IN];    // h * norm_src
__device__ float g_agg1[(size_t)N_NODES * F_IN];
__device__ float g_h1  [(size_t)N_NODES * F_MID];
__device__ float g_t2  [(size_t)N_NODES * F_IN];

// ---------------- f32x2 helpers (FFMA2 path, fp32-exact) ----------------
typedef unsigned long long u64;

__device__ __forceinline__ u64 pack2(float lo, float hi) {
    u64 r; asm("mov.b64 %0, {%1,%2};" : "=l"(r) : "f"(lo), "f"(hi)); return r;
}
__device__ __forceinline__ void fma2(u64& d, u64 a, u64 b) {
    asm("fma.rn.f32x2 %0, %1, %2, %0;" : "+l"(d) : "l"(a), "l"(b));
}
__device__ __forceinline__ float2 unpack2(u64 v) {
    float2 r; asm("mov.b64 {%0,%1}, %2;" : "=f"(r.x), "=f"(r.y) : "l"(v)); return r;
}

// ---------------- kernels ----------------

__global__ void zero_kernel() {
    int i = blockIdx.x * blockDim.x + threadIdx.x;
    if (i < N_NODES) { g_deg_out[i] = 0; g_deg_in[i] = 0; }
    if (i == 0) g_alloc = 0;
}

// Degrees, 4 edges/thread (int4 loads, 8 independent atomics in flight).
// The in-degree atomic's return value is this edge's bucket rank (free).
__global__ void degree_kernel(const int* __restrict__ src,
                              const int* __restrict__ dst) {
    int t = blockIdx.x * blockDim.x + threadIdx.x;     // 0 .. N_EDGES/4-1
    if (t >= N_EDGES / 4) return;
    int4 s = __ldg(reinterpret_cast<const int4*>(src) + t);
    int4 d = __ldg(reinterpret_cast<const int4*>(dst) + t);
    atomicAdd(&g_deg_out[s.x], 1);
    atomicAdd(&g_deg_out[s.y], 1);
    atomicAdd(&g_deg_out[s.z], 1);
    atomicAdd(&g_deg_out[s.w], 1);
    int4 r;
    r.x = atomicAdd(&g_deg_in[d.x], 1);
    r.y = atomicAdd(&g_deg_in[d.y], 1);
    r.z = atomicAdd(&g_deg_in[d.z], 1);
    r.w = atomicAdd(&g_deg_in[d.w], 1);
    reinterpret_cast<int4*>(g_rank)[t] = r;
}

// Per-block smem scan of deg_in + single atomic per block for CSR bucket offsets.
// Also computes both norms.
__global__ __launch_bounds__(256) void norm_offset_kernel() {
    __shared__ int s[256];
    __shared__ int base;
    int t = threadIdx.x;
    int i = blockIdx.x * 256 + t;
    int deg = 0, dout = 0;
    if (i < N_NODES) { deg = g_deg_in[i]; dout = g_deg_out[i]; }
    s[t] = deg;
    __syncthreads();
#pragma unroll
    for (int o = 1; o < 256; o <<= 1) {
        int v = (t >= o) ? s[t - o] : 0;
        __syncthreads();
        s[t] += v;
        __syncthreads();
    }
    if (t == 255) base = atomicAdd(&g_alloc, s[255]);
    __syncthreads();
    if (i < N_NODES) {
        g_off[i] = base + s[t] - deg;     // exclusive scan + block base
        g_norm_src[i] = rsqrtf(fmaxf((float)dout, 1.f));
        g_norm_dst[i] = rsqrtf(fmaxf((float)deg,  1.f));
    }
}

// Atomic-free CSR fill, 4 edges/thread (4 independent scatter stores in flight).
__global__ void fill_kernel(const int* __restrict__ src,
                            const int* __restrict__ dst) {
    int t = blockIdx.x * blockDim.x + threadIdx.x;
    if (t >= N_EDGES / 4) return;
    int4 s = __ldg(reinterpret_cast<const int4*>(src) + t);
    int4 d = __ldg(reinterpret_cast<const int4*>(dst) + t);
    int4 r = *(reinterpret_cast<const int4*>(g_rank) + t);
    int px = __ldg(&g_off[d.x]) + r.x;
    int py = __ldg(&g_off[d.y]) + r.y;
    int pz = __ldg(&g_off[d.z]) + r.z;
    int pw = __ldg(&g_off[d.w]) + r.w;
    g_esrc[px] = s.x;
    g_esrc[py] = s.y;
    g_esrc[pz] = s.z;
    g_esrc[pw] = s.w;
}

// hs = h * norm_src   (float4)
__global__ void prescale_kernel(const float* __restrict__ h) {
    int i = blockIdx.x * blockDim.x + threadIdx.x;
    const int NF4 = N_NODES * F_IN / 4;
    if (i >= NF4) return;
    float ns = g_norm_src[i >> 4];
    float4 v = reinterpret_cast<const float4*>(h)[i];
    v.x *= ns; v.y *= ns; v.z *= ns; v.w *= ns;
    reinterpret_cast<float4*>(g_hs)[i] = v;
}

// Accumulate one source row chunk (2 float4) into (a0,a1).
__device__ __forceinline__ void acc_row(const float4* __restrict__ base4, int s, int c2,
                                        float4& a0, float4& a1) {
    const float4* p = base4 + (size_t)s * 16 + c2;
    float4 v0 = __ldg(p), v1 = __ldg(p + 1);
    a0.x += v0.x; a0.y += v0.y; a0.z += v0.z; a0.w += v0.w;
    a1.x += v1.x; a1.y += v1.y; a1.z += v1.z; a1.w += v1.w;
}

// Pull-aggregation layer 1: agg1[n] = sum over incoming edges of hs[src].
__global__ void aggregate1_kernel() {
    int tid = blockIdx.x * blockDim.x + threadIdx.x;
    int n = tid >> 3;
    if (n >= N_NODES) return;
    int c2 = (tid & 7) << 1;
    int i   = __ldg(&g_off[n]);
    int end = i + __ldg(&g_deg_in[n]);
    const float4* hs4 = reinterpret_cast<const float4*>(g_hs);
    float4 a0 = make_float4(0.f,0.f,0.f,0.f);
    float4 a1 = a0;
    while ((i & 3) && i < end) acc_row(hs4, __ldg(&g_esrc[i++]), c2, a0, a1);
    const int4* e4 = reinterpret_cast<const int4*>(g_esrc);
    for (; i + 4 <= end; i += 4) {
        int4 q = __ldg(&e4[i >> 2]);
        acc_row(hs4, q.x, c2, a0, a1);
        acc_row(hs4, q.y, c2, a0, a1);
        acc_row(hs4, q.z, c2, a0, a1);
        acc_row(hs4, q.w, c2, a0, a1);
    }
    for (; i < end; i++) acc_row(hs4, __ldg(&g_esrc[i]), c2, a0, a1);
    float4* o = reinterpret_cast<float4*>(g_agg1) + (size_t)n * 16 + c2;
    o[0] = a0; o[1] = a1;
}

// h1 = relu(norm_dst ⊙ (agg1 @ W1) + b1)
// Block: 64 rows x 128 cols, 256 threads, thread tile 8x4, FFMA2 accumulators.
// acc[rp][c] holds rows (2rp, 2rp+1) of column c as packed f32x2.
__global__ __launch_bounds__(256) void gemm1_kernel(const float* __restrict__ W1,
                                                    const float* __restrict__ b1) {
    __shared__ __align__(16) float Ws[F_IN * F_MID];   // [k][col], 32 KB
    __shared__ __align__(16) float As[F_IN][68];       // transposed: [k][row], 64 rows
    int t  = threadIdx.x;
    int ct = t & 31;    // cols ct*4
    int rt = t >> 5;    // rows rt*8 .. rt*8+7
    int row0 = blockIdx.x * 64;

    for (int i = t; i < F_IN * F_MID / 4; i += 256)
        reinterpret_cast<float4*>(Ws)[i] = reinterpret_cast<const float4*>(W1)[i];

    for (int i = t; i < 64 * F_IN / 4; i += 256) {
        int r  = i >> 4;
        int c4 = (i & 15) << 2;
        int row = row0 + r;
        float4 v = (row < N_NODES)
            ? *reinterpret_cast<const float4*>(g_agg1 + (size_t)row * F_IN + c4)
            : make_float4(0.f, 0.f, 0.f, 0.f);
        As[c4 + 0][r] = v.x; As[c4 + 1][r] = v.y;
        As[c4 + 2][r] = v.z; As[c4 + 3][r] = v.w;
    }
    __syncthreads();

    u64 acc[4][4];
#pragma unroll
    for (int rp = 0; rp < 4; rp++)
#pragma unroll
        for (int c = 0; c < 4; c++) acc[rp][c] = 0ull;

#pragma unroll 8
    for (int k = 0; k < F_IN; k++) {
        float4 w  = *reinterpret_cast<const float4*>(&Ws[k * F_MID + (ct << 2)]);
        float4 aA = *reinterpret_cast<const float4*>(&As[k][rt << 3]);
        float4 aB = *reinterpret_cast<const float4*>(&As[k][(rt << 3) + 4]);
        u64 wp[4] = { pack2(w.x, w.x), pack2(w.y, w.y), pack2(w.z, w.z), pack2(w.w, w.w) };
        u64 ap[4] = { pack2(aA.x, aA.y), pack2(aA.z, aA.w),
                      pack2(aB.x, aB.y), pack2(aB.z, aB.w) };
#pragma unroll
        for (int rp = 0; rp < 4; rp++) {
            fma2(acc[rp][0], ap[rp], wp[0]);
            fma2(acc[rp][1], ap[rp], wp[1]);
            fma2(acc[rp][2], ap[rp], wp[2]);
            fma2(acc[rp][3], ap[rp], wp[3]);
        }
    }

    float4 bb = *reinterpret_cast<const float4*>(b1 + (ct << 2));
#pragma unroll
    for (int rp = 0; rp < 4; rp++) {
        float2 c0 = unpack2(acc[rp][0]);
        float2 c1 = unpack2(acc[rp][1]);
        float2 c2v = unpack2(acc[rp][2]);
        float2 c3 = unpack2(acc[rp][3]);
#pragma unroll
        for (int half = 0; half < 2; half++) {
            int row = row0 + (rt << 3) + (rp << 1) + half;
            if (row >= N_NODES) break;
            float nd = g_norm_dst[row];
            float4 o;
            o.x = fmaxf(fmaf(half ? c0.y : c0.x, nd, bb.x), 0.f);
            o.y = fmaxf(fmaf(half ? c1.y : c1.x, nd, bb.y), 0.f);
            o.z = fmaxf(fmaf(half ? c2v.y : c2v.x, nd, bb.z), 0.f);
            o.w = fmaxf(fmaf(half ? c3.y : c3.x, nd, bb.w), 0.f);
            *reinterpret_cast<float4*>(g_h1 + (size_t)row * F_MID + (ct << 2)) = o;
        }
    }
}

// t2 = norm_src ⊙ (h1 @ W2)   — 64 rows x 64 cols / block, 4x4 tile, FFMA2.
__global__ __launch_bounds__(256) void gemm2_kernel(const float* __restrict__ W2) {
    __shared__ __align__(16) float Ws[F_MID * F_IN];   // 32 KB
    __shared__ __align__(16) float As[F_MID][68];
    int t  = threadIdx.x;
    int ct = t & 15;
    int rt = t >> 4;
    int row0 = blockIdx.x * 64;

    for (int i = t; i < F_MID * F_IN / 4; i += 256)
        reinterpret_cast<float4*>(Ws)[i] = reinterpret_cast<const float4*>(W2)[i];

    for (int i = t; i < 64 * F_MID / 4; i += 256) {
        int r  = i >> 5;
        int c4 = (i & 31) << 2;
        int row = row0 + r;
        float4 v = (row < N_NODES)
            ? *reinterpret_cast<const float4*>(g_h1 + (size_t)row * F_MID + c4)
            : make_float4(0.f, 0.f, 0.f, 0.f);
        As[c4 + 0][r] = v.x; As[c4 + 1][r] = v.y;
        As[c4 + 2][r] = v.z; As[c4 + 3][r] = v.w;
    }
    __syncthreads();

    u64 acc[2][4];
#pragma unroll
    for (int rp = 0; rp < 2; rp++)
#pragma unroll
        for (int c = 0; c < 4; c++) acc[rp][c] = 0ull;

#pragma unroll 8
    for (int k = 0; k < F_MID; k++) {
        float4 w = *reinterpret_cast<const float4*>(&Ws[k * F_IN + (ct << 2)]);
        float4 a = *reinterpret_cast<const float4*>(&As[k][rt << 2]);
        u64 wp[4] = { pack2(w.x, w.x), pack2(w.y, w.y), pack2(w.z, w.z), pack2(w.w, w.w) };
        u64 ap[2] = { pack2(a.x, a.y), pack2(a.z, a.w) };
#pragma unroll
        for (int rp = 0; rp < 2; rp++) {
            fma2(acc[rp][0], ap[rp], wp[0]);
            fma2(acc[rp][1], ap[rp], wp[1]);
            fma2(acc[rp][2], ap[rp], wp[2]);
            fma2(acc[rp][3], ap[rp], wp[3]);
        }
    }

#pragma unroll
    for (int rp = 0; rp < 2; rp++) {
        float2 c0 = unpack2(acc[rp][0]);
        float2 c1 = unpack2(acc[rp][1]);
        float2 c2v = unpack2(acc[rp][2]);
        float2 c3 = unpack2(acc[rp][3]);
#pragma unroll
        for (int half = 0; half < 2; half++) {
            int row = row0 + (rt << 2) + (rp << 1) + half;
            if (row >= N_NODES) break;
            float ns = g_norm_src[row];
            float4 o;
            o.x = (half ? c0.y : c0.x) * ns;
            o.y = (half ? c1.y : c1.x) * ns;
            o.z = (half ? c2v.y : c2v.x) * ns;
            o.w = (half ? c3.y : c3.x) * ns;
            *reinterpret_cast<float4*>(g_t2 + (size_t)row * F_IN + (ct << 2)) = o;
        }
    }
}

// Pull-aggregation layer 2 + fused epilogue: out[n] = (sum t2[src]) * norm_dst[n] + b2
__global__ void aggregate2_kernel(const float* __restrict__ b2,
                                  float* __restrict__ out) {
    int tid = blockIdx.x * blockDim.x + threadIdx.x;
    int n = tid >> 3;
    if (n >= N_NODES) return;
    int c2 = (tid & 7) << 1;
    int i   = __ldg(&g_off[n]);
    int end = i + __ldg(&g_deg_in[n]);
    const float4* t4 = reinterpret_cast<const float4*>(g_t2);
    float4 a0 = make_float4(0.f,0.f,0.f,0.f);
    float4 a1 = a0;
    while ((i & 3) && i < end) acc_row(t4, __ldg(&g_esrc[i++]), c2, a0, a1);
    const int4* e4 = reinterpret_cast<const int4*>(g_esrc);
    for (; i + 4 <= end; i += 4) {
        int4 q = __ldg(&e4[i >> 2]);
        acc_row(t4, q.x, c2, a0, a1);
        acc_row(t4, q.y, c2, a0, a1);
        acc_row(t4, q.z, c2, a0, a1);
        acc_row(t4, q.w, c2, a0, a1);
    }
    for (; i < end; i++) acc_row(t4, __ldg(&g_esrc[i]), c2, a0, a1);

    float nd = g_norm_dst[n];
    float4 b0 = reinterpret_cast<const float4*>(b2)[c2];
    float4 b1v = reinterpret_cast<const float4*>(b2)[c2 + 1];
    float4 o0, o1;
    o0.x = fmaf(a0.x, nd, b0.x);  o0.y = fmaf(a0.y, nd, b0.y);
    o0.z = fmaf(a0.z, nd, b0.z);  o0.w = fmaf(a0.w, nd, b0.w);
    o1.x = fmaf(a1.x, nd, b1v.x); o1.y = fmaf(a1.y, nd, b1v.y);
    o1.z = fmaf(a1.z, nd, b1v.z); o1.w = fmaf(a1.w, nd, b1v.w);
    float4* o = reinterpret_cast<float4*>(out) + (size_t)n * 16 + c2;
    o[0] = o0; o[1] = o1;
}

// ---------------- launch ----------------
extern "C" void kernel_launch(void* const* d_in, const int* in_sizes, int n_in,
                              void* d_out, int out_size) {
    const float* h   = (const float*)d_in[0];
    const int*   src = (const int*)  d_in[1];
    const int*   dst = (const int*)  d_in[2];
    const float* W1  = (const float*)d_in[3];
    const float* b1  = (const float*)d_in[4];
    const float* W2  = (const float*)d_in[5];
    const float* b2  = (const float*)d_in[6];
    float* out = (float*)d_out;

    zero_kernel<<<(N_NODES + 255) / 256, 256>>>();
    degree_kernel<<<(N_EDGES / 4 + 255) / 256, 256>>>(src, dst);
    norm_offset_kernel<<<(N_NODES + 255) / 256, 256>>>();
    fill_kernel<<<(N_EDGES / 4 + 255) / 256, 256>>>(src, dst);

    const int NF4 = N_NODES * F_IN / 4;
    prescale_kernel<<<(NF4 + 255) / 256, 256>>>(h);

    const int a_threads = N_NODES * 8;
    aggregate1_kernel<<<(a_threads + 255) / 256, 256>>>();

    gemm1_kernel<<<(N_NODES + 63) / 64, 256>>>(W1, b1);
    gemm2_kernel<<<(N_NODES + 63) / 64, 256>>>(W2);

    aggregate2_kernel<<<(a_threads + 255) / 256, 256>>>(b2, out);
}

// round 9
// speedup vs baseline: 1.8751x; 1.0123x over previous
#include <cuda_runtime.h>
#include <cuda_bf16.h>
#include <cstdint>

#define N_NODES 50000
#define N_EDGES 800000
#define F_IN    64
#define F_MID   128
#define GTILE   64           // rows per fused-GEMM tile
#define NTILES  ((N_NODES + GTILE - 1) / GTILE)   // 782

// ---------------- scratch (device globals; no allocations) ----------------
__device__ int   g_deg_out[N_NODES];
__device__ int   g_deg_in [N_NODES];
__device__ float g_norm_src[N_NODES];
__device__ float g_norm_dst[N_NODES];
__device__ int   g_off [N_NODES];
__device__ int   g_alloc;
__device__ int   g_rank[N_EDGES];                   // rank of edge within its dst bucket
__device__ int   g_esrc[N_EDGES];                   // src ids bucketed by dst
__device__ float g_hs  [(size_t)N_NODES * F_IN];    // h * norm_src
__device__ float g_agg1[(size_t)N_NODES * F_IN];
__device__ float g_t2  [(size_t)N_NODES * F_IN];

// Dynamic smem layout for fused GEMM (float offsets)
#define WS1_OFF 0                              // [64*128]   8192
#define WS2_OFF 8192                           // [128*64]   8192
#define AS_OFF  16384                          // [k=64][row pad 68] 4352
#define H1_OFF  (16384 + 64*68)                // [row=64][col pad 132] 8448
#define SMEM_FLOATS (H1_OFF + 64*132)          // 29184
#define SMEM_BYTES (SMEM_FLOATS * 4)           // 116736

// ---------------- kernels ----------------

__global__ void zero_kernel() {
    int i = blockIdx.x * blockDim.x + threadIdx.x;
    if (i < N_NODES) { g_deg_out[i] = 0; g_deg_in[i] = 0; }
    if (i == 0) g_alloc = 0;
}

// Degrees, 2 edges/thread. In-degree atomic's return = edge's bucket rank (free).
__global__ void degree_kernel(const int* __restrict__ src,
                              const int* __restrict__ dst) {
    int t = blockIdx.x * blockDim.x + threadIdx.x;
    if (t >= N_EDGES / 2) return;
    int2 s = __ldg(reinterpret_cast<const int2*>(src) + t);
    int2 d = __ldg(reinterpret_cast<const int2*>(dst) + t);
    atomicAdd(&g_deg_out[s.x], 1);
    atomicAdd(&g_deg_out[s.y], 1);
    int2 r;
    r.x = atomicAdd(&g_deg_in[d.x], 1);
    r.y = atomicAdd(&g_deg_in[d.y], 1);
    reinterpret_cast<int2*>(g_rank)[t] = r;
}

// Scan for CSR offsets + norms + fused prescale of this block's 256 rows.
__global__ __launch_bounds__(256) void norm_offset_prescale_kernel(const float* __restrict__ h) {
    __shared__ int   s[256];
    __shared__ int   base;
    __shared__ float ns_s[256];
    int t = threadIdx.x;
    int i = blockIdx.x * 256 + t;
    int deg = 0, dout = 0;
    if (i < N_NODES) { deg = g_deg_in[i]; dout = g_deg_out[i]; }
    s[t] = deg;
    __syncthreads();
#pragma unroll
    for (int o = 1; o < 256; o <<= 1) {
        int v = (t >= o) ? s[t - o] : 0;
        __syncthreads();
        s[t] += v;
        __syncthreads();
    }
    if (t == 255) base = atomicAdd(&g_alloc, s[255]);
    float nsv = rsqrtf(fmaxf((float)dout, 1.f));
    ns_s[t] = nsv;
    __syncthreads();
    if (i < N_NODES) {
        g_off[i] = base + s[t] - deg;
        g_norm_src[i] = nsv;
        g_norm_dst[i] = rsqrtf(fmaxf((float)deg, 1.f));
    }
    // prescale: hs = h * norm_src for this block's 256 rows (16 float4 per row)
    int base_row = blockIdx.x * 256;
    const float4* h4 = reinterpret_cast<const float4*>(h);
    float4* hs4 = reinterpret_cast<float4*>(g_hs);
#pragma unroll
    for (int j = 0; j < 16; j++) {
        int idx = j * 256 + t;          // 0..4095
        int lr = idx >> 4;
        int c4 = idx & 15;
        int row = base_row + lr;
        if (row < N_NODES) {
            float ns = ns_s[lr];
            float4 v = __ldg(&h4[(size_t)row * 16 + c4]);
            v.x *= ns; v.y *= ns; v.z *= ns; v.w *= ns;
            hs4[(size_t)row * 16 + c4] = v;
        }
    }
}

// Atomic-free CSR fill, 2 edges/thread.
__global__ void fill_kernel(const int* __restrict__ src,
                            const int* __restrict__ dst) {
    int t = blockIdx.x * blockDim.x + threadIdx.x;
    if (t >= N_EDGES / 2) return;
    int2 s = __ldg(reinterpret_cast<const int2*>(src) + t);
    int2 d = __ldg(reinterpret_cast<const int2*>(dst) + t);
    int2 r = *(reinterpret_cast<const int2*>(g_rank) + t);
    int px = __ldg(&g_off[d.x]) + r.x;
    int py = __ldg(&g_off[d.y]) + r.y;
    g_esrc[px] = s.x;
    g_esrc[py] = s.y;
}

// Accumulate one source row chunk (2 float4) into (a0,a1).
__device__ __forceinline__ void acc_row(const float4* __restrict__ base4, int s, int c2,
                                        float4& a0, float4& a1) {
    const float4* p = base4 + (size_t)s * 16 + c2;
    float4 v0 = __ldg(p), v1 = __ldg(p + 1);
    a0.x += v0.x; a0.y += v0.y; a0.z += v0.z; a0.w += v0.w;
    a1.x += v1.x; a1.y += v1.y; a1.z += v1.z; a1.w += v1.w;
}

// Pull-aggregation layer 1: agg1[n] = sum over incoming edges of hs[src].
__global__ void aggregate1_kernel() {
    int tid = blockIdx.x * blockDim.x + threadIdx.x;
    int n = tid >> 3;
    if (n >= N_NODES) return;
    int c2 = (tid & 7) << 1;
    int i   = __ldg(&g_off[n]);
    int end = i + __ldg(&g_deg_in[n]);
    const float4* hs4 = reinterpret_cast<const float4*>(g_hs);
    float4 a0 = make_float4(0.f,0.f,0.f,0.f);
    float4 a1 = a0;
    while ((i & 3) && i < end) acc_row(hs4, __ldg(&g_esrc[i++]), c2, a0, a1);
    const int4* e4 = reinterpret_cast<const int4*>(g_esrc);
    for (; i + 4 <= end; i += 4) {
        int4 q = __ldg(&e4[i >> 2]);
        acc_row(hs4, q.x, c2, a0, a1);
        acc_row(hs4, q.y, c2, a0, a1);
        acc_row(hs4, q.z, c2, a0, a1);
        acc_row(hs4, q.w, c2, a0, a1);
    }
    for (; i < end; i++) acc_row(hs4, __ldg(&g_esrc[i]), c2, a0, a1);
    float4* o = reinterpret_cast<float4*>(g_agg1) + (size_t)n * 16 + c2;
    o[0] = a0; o[1] = a1;
}

// Fused persistent GEMM: per 64-row tile,
//   phase1: h1 = relu(norm_dst ⊙ (agg1 @ W1) + b1)  -> smem H1s (row-major)
//   phase2: t2 = norm_src ⊙ (h1 @ W2)               -> gmem
// 512 threads, grid = 148 (persistent), weights loaded once per block.
__global__ __launch_bounds__(512) void fused_gemm_kernel(const float* __restrict__ W1,
                                                         const float* __restrict__ b1,
                                                         const float* __restrict__ W2) {
    extern __shared__ __align__(16) float sm[];
    float* Ws1 = sm + WS1_OFF;
    float* Ws2 = sm + WS2_OFF;
    float* As  = sm + AS_OFF;     // transposed [k][row], pad 68
    float* H1s = sm + H1_OFF;     // row-major [row][col], pad 132
    int t = threadIdx.x;

    // Load both weight matrices once.
    for (int i = t; i < F_IN * F_MID / 4; i += 512)
        reinterpret_cast<float4*>(Ws1)[i] = __ldg(reinterpret_cast<const float4*>(W1) + i);
    for (int i = t; i < F_MID * F_IN / 4; i += 512)
        reinterpret_cast<float4*>(Ws2)[i] = __ldg(reinterpret_cast<const float4*>(W2) + i);

    // phase1 mapping: ct (cols 4*ct of 128), rt (rows 4*rt of 64)
    int ct = t & 31;
    int rt = t >> 5;
    // phase2 mapping: ct2 (cols 4*ct2 of 64), rt2 (rows 2*rt2 of 64)
    int ct2 = t & 15;
    int rt2 = t >> 4;

    float4 bb = __ldg(reinterpret_cast<const float4*>(b1) + ct);

    for (int tile = blockIdx.x; tile < NTILES; tile += gridDim.x) {
        int row0 = tile * GTILE;
        __syncthreads();   // previous iteration fully done (As/H1s safe to overwrite)

        // Load A tile (agg1 rows) transposed into As[k][row]
        for (int i = t; i < GTILE * F_IN / 4; i += 512) {
            int r  = i >> 4;
            int c4 = (i & 15) << 2;
            int row = row0 + r;
            float4 v = (row < N_NODES)
                ? *reinterpret_cast<const float4*>(g_agg1 + (size_t)row * F_IN + c4)
                : make_float4(0.f, 0.f, 0.f, 0.f);
            As[(c4 + 0) * 68 + r] = v.x;
            As[(c4 + 1) * 68 + r] = v.y;
            As[(c4 + 2) * 68 + r] = v.z;
            As[(c4 + 3) * 68 + r] = v.w;
        }
        __syncthreads();

        // ---- phase 1: 4 rows x 4 cols per thread ----
        float acc[4][4];
#pragma unroll
        for (int j = 0; j < 4; j++)
#pragma unroll
            for (int c = 0; c < 4; c++) acc[j][c] = 0.f;

#pragma unroll 8
        for (int k = 0; k < F_IN; k++) {
            float4 w = *reinterpret_cast<const float4*>(&Ws1[k * F_MID + (ct << 2)]);
            float4 a = *reinterpret_cast<const float4*>(&As[k * 68 + (rt << 2)]);
            float av[4] = {a.x, a.y, a.z, a.w};
#pragma unroll
            for (int j = 0; j < 4; j++) {
                acc[j][0] = fmaf(av[j], w.x, acc[j][0]);
                acc[j][1] = fmaf(av[j], w.y, acc[j][1]);
                acc[j][2] = fmaf(av[j], w.z, acc[j][2]);
                acc[j][3] = fmaf(av[j], w.w, acc[j][3]);
            }
        }
#pragma unroll
        for (int j = 0; j < 4; j++) {
            int lr = (rt << 2) + j;
            int row = row0 + lr;
            float nd = (row < N_NODES) ? __ldg(&g_norm_dst[row]) : 0.f;
            float4 o;
            o.x = fmaxf(fmaf(acc[j][0], nd, bb.x), 0.f);
            o.y = fmaxf(fmaf(acc[j][1], nd, bb.y), 0.f);
            o.z = fmaxf(fmaf(acc[j][2], nd, bb.z), 0.f);
            o.w = fmaxf(fmaf(acc[j][3], nd, bb.w), 0.f);
            *reinterpret_cast<float4*>(&H1s[lr * 132 + (ct << 2)]) = o;
        }
        __syncthreads();

        // ---- phase 2: 2 rows x 4 cols per thread ----
        float acc2[2][4];
#pragma unroll
        for (int j = 0; j < 2; j++)
#pragma unroll
            for (int c = 0; c < 4; c++) acc2[j][c] = 0.f;

        int r0 = rt2 << 1;
#pragma unroll 8
        for (int k = 0; k < F_MID; k++) {
            float4 w = *reinterpret_cast<const float4*>(&Ws2[k * F_IN + (ct2 << 2)]);
            float a0 = H1s[r0 * 132 + k];          // broadcast across 16 lanes
            float a1 = H1s[(r0 + 1) * 132 + k];
            acc2[0][0] = fmaf(a0, w.x, acc2[0][0]);
            acc2[0][1] = fmaf(a0, w.y, acc2[0][1]);
            acc2[0][2] = fmaf(a0, w.z, acc2[0][2]);
            acc2[0][3] = fmaf(a0, w.w, acc2[0][3]);
            acc2[1][0] = fmaf(a1, w.x, acc2[1][0]);
            acc2[1][1] = fmaf(a1, w.y, acc2[1][1]);
            acc2[1][2] = fmaf(a1, w.z, acc2[1][2]);
            acc2[1][3] = fmaf(a1, w.w, acc2[1][3]);
        }
#pragma unroll
        for (int j = 0; j < 2; j++) {
            int row = row0 + r0 + j;
            if (row < N_NODES) {
                float ns = __ldg(&g_norm_src[row]);
                float4 o;
                o.x = acc2[j][0] * ns; o.y = acc2[j][1] * ns;
                o.z = acc2[j][2] * ns; o.w = acc2[j][3] * ns;
                *reinterpret_cast<float4*>(g_t2 + (size_t)row * F_IN + (ct2 << 2)) = o;
            }
        }
    }
}

// Pull-aggregation layer 2 + fused epilogue: out[n] = (sum t2[src]) * norm_dst[n] + b2
__global__ void aggregate2_kernel(const float* __restrict__ b2,
                                  float* __restrict__ out) {
    int tid = blockIdx.x * blockDim.x + threadIdx.x;
    int n = tid >> 3;
    if (n >= N_NODES) return;
    int c2 = (tid & 7) << 1;
    int i   = __ldg(&g_off[n]);
    int end = i + __ldg(&g_deg_in[n]);
    const float4* t4 = reinterpret_cast<const float4*>(g_t2);
    float4 a0 = make_float4(0.f,0.f,0.f,0.f);
    float4 a1 = a0;
    while ((i & 3) && i < end) acc_row(t4, __ldg(&g_esrc[i++]), c2, a0, a1);
    const int4* e4 = reinterpret_cast<const int4*>(g_esrc);
    for (; i + 4 <= end; i += 4) {
        int4 q = __ldg(&e4[i >> 2]);
        acc_row(t4, q.x, c2, a0, a1);
        acc_row(t4, q.y, c2, a0, a1);
        acc_row(t4, q.z, c2, a0, a1);
        acc_row(t4, q.w, c2, a0, a1);
    }
    for (; i < end; i++) acc_row(t4, __ldg(&g_esrc[i]), c2, a0, a1);

    float nd = g_norm_dst[n];
    float4 b0 = reinterpret_cast<const float4*>(b2)[c2];
    float4 b1v = reinterpret_cast<const float4*>(b2)[c2 + 1];
    float4 o0, o1;
    o0.x = fmaf(a0.x, nd, b0.x);  o0.y = fmaf(a0.y, nd, b0.y);
    o0.z = fmaf(a0.z, nd, b0.z);  o0.w = fmaf(a0.w, nd, b0.w);
    o1.x = fmaf(a1.x, nd, b1v.x); o1.y = fmaf(a1.y, nd, b1v.y);
    o1.z = fmaf(a1.z, nd, b1v.z); o1.w = fmaf(a1.w, nd, b1v.w);
    float4* o = reinterpret_cast<float4*>(out) + (size_t)n * 16 + c2;
    o[0] = o0; o[1] = o1;
}

// ---------------- launch ----------------
extern "C" void kernel_launch(void* const* d_in, const int* in_sizes, int n_in,
                              void* d_out, int out_size) {
    const float* h   = (const float*)d_in[0];
    const int*   src = (const int*)  d_in[1];
    const int*   dst = (const int*)  d_in[2];
    const float* W1  = (const float*)d_in[3];
    const float* b1  = (const float*)d_in[4];
    const float* W2  = (const float*)d_in[5];
    const float* b2  = (const float*)d_in[6];
    float* out = (float*)d_out;

    cudaFuncSetAttribute(fused_gemm_kernel,
                         cudaFuncAttributeMaxDynamicSharedMemorySize, SMEM_BYTES);

    zero_kernel<<<(N_NODES + 255) / 256, 256>>>();
    degree_kernel<<<(N_EDGES / 2 + 255) / 256, 256>>>(src, dst);
    norm_offset_prescale_kernel<<<(N_NODES + 255) / 256, 256>>>(h);
    fill_kernel<<<(N_EDGES / 2 + 255) / 256, 256>>>(src, dst);

    const int a_threads = N_NODES * 8;
    aggregate1_kernel<<<(a_threads + 255) / 256, 256>>>();

    fused_gemm_kernel<<<148, 512, SMEM_BYTES>>>(W1, b1, W2);

    aggregate2_kernel<<<(a_threads + 255) / 256, 256>>>(b2, out);
}

// round 10
// speedup vs baseline: 2.0007x; 1.0670x over previous
#include <cuda_runtime.h>
#include <cuda_bf16.h>
#include <cstdint>

#define N_NODES 50000
#define N_EDGES 800000
#define F_IN    64
#define F_MID   128
#define GTILE   128          // rows per fused-GEMM tile
#define NTILES  ((N_NODES + GTILE - 1) / GTILE)   // 391

// ---------------- scratch (device globals; no allocations) ----------------
__device__ int   g_deg_out[N_NODES];
__device__ int   g_deg_in [N_NODES];
__device__ float g_norm_src[N_NODES];
__device__ float g_norm_dst[N_NODES];
__device__ int   g_off [N_NODES];
__device__ int   g_alloc;
__device__ int   g_rank[N_EDGES];                   // rank of edge within its dst bucket
__device__ int   g_esrc[N_EDGES];                   // src ids bucketed by dst
__device__ float g_hs  [(size_t)N_NODES * F_IN];    // h * norm_src
__device__ float g_agg1[(size_t)N_NODES * F_IN];
__device__ float g_t2  [(size_t)N_NODES * F_IN];

// Dynamic smem layout for fused GEMM (float offsets)
#define WS1_OFF 0                              // [64*128]          8192 floats
#define WS2_OFF 8192                           // [128*64]          8192 floats
#define AS_OFF  16384                          // [128 rows][64 k]  8192 floats (row-major)
#define H1_OFF  24576                          // [128 rows][132]  16896 floats
#define SMEM_FLOATS (H1_OFF + GTILE * 132)     // 41472
#define SMEM_BYTES (SMEM_FLOATS * 4)           // 165888

// ---------------- kernels ----------------

__global__ void zero_kernel() {
    int i = blockIdx.x * blockDim.x + threadIdx.x;
    if (i < N_NODES) { g_deg_out[i] = 0; g_deg_in[i] = 0; }
    if (i == 0) g_alloc = 0;
}

// Degrees, 2 edges/thread. In-degree atomic's return = edge's bucket rank (free).
__global__ void degree_kernel(const int* __restrict__ src,
                              const int* __restrict__ dst) {
    int t = blockIdx.x * blockDim.x + threadIdx.x;
    if (t >= N_EDGES / 2) return;
    int2 s = __ldg(reinterpret_cast<const int2*>(src) + t);
    int2 d = __ldg(reinterpret_cast<const int2*>(dst) + t);
    atomicAdd(&g_deg_out[s.x], 1);
    atomicAdd(&g_deg_out[s.y], 1);
    int2 r;
    r.x = atomicAdd(&g_deg_in[d.x], 1);
    r.y = atomicAdd(&g_deg_in[d.y], 1);
    reinterpret_cast<int2*>(g_rank)[t] = r;
}

// Scan for CSR offsets + norms + fused prescale of this block's 256 rows.
__global__ __launch_bounds__(256) void norm_offset_prescale_kernel(const float* __restrict__ h) {
    __shared__ int   s[256];
    __shared__ int   base;
    __shared__ float ns_s[256];
    int t = threadIdx.x;
    int i = blockIdx.x * 256 + t;
    int deg = 0, dout = 0;
    if (i < N_NODES) { deg = g_deg_in[i]; dout = g_deg_out[i]; }
    s[t] = deg;
    __syncthreads();
#pragma unroll
    for (int o = 1; o < 256; o <<= 1) {
        int v = (t >= o) ? s[t - o] : 0;
        __syncthreads();
        s[t] += v;
        __syncthreads();
    }
    if (t == 255) base = atomicAdd(&g_alloc, s[255]);
    float nsv = rsqrtf(fmaxf((float)dout, 1.f));
    ns_s[t] = nsv;
    __syncthreads();
    if (i < N_NODES) {
        g_off[i] = base + s[t] - deg;
        g_norm_src[i] = nsv;
        g_norm_dst[i] = rsqrtf(fmaxf((float)deg, 1.f));
    }
    // prescale: hs = h * norm_src for this block's 256 rows (16 float4 per row)
    int base_row = blockIdx.x * 256;
    const float4* h4 = reinterpret_cast<const float4*>(h);
    float4* hs4 = reinterpret_cast<float4*>(g_hs);
#pragma unroll
    for (int j = 0; j < 16; j++) {
        int idx = j * 256 + t;          // 0..4095
        int lr = idx >> 4;
        int c4 = idx & 15;
        int row = base_row + lr;
        if (row < N_NODES) {
            float ns = ns_s[lr];
            float4 v = __ldg(&h4[(size_t)row * 16 + c4]);
            v.x *= ns; v.y *= ns; v.z *= ns; v.w *= ns;
            hs4[(size_t)row * 16 + c4] = v;
        }
    }
}

// Atomic-free CSR fill, 2 edges/thread.
__global__ void fill_kernel(const int* __restrict__ src,
                            const int* __restrict__ dst) {
    int t = blockIdx.x * blockDim.x + threadIdx.x;
    if (t >= N_EDGES / 2) return;
    int2 s = __ldg(reinterpret_cast<const int2*>(src) + t);
    int2 d = __ldg(reinterpret_cast<const int2*>(dst) + t);
    int2 r = *(reinterpret_cast<const int2*>(g_rank) + t);
    int px = __ldg(&g_off[d.x]) + r.x;
    int py = __ldg(&g_off[d.y]) + r.y;
    g_esrc[px] = s.x;
    g_esrc[py] = s.y;
}

// Accumulate one source row chunk (2 float4) into (a0,a1).
__device__ __forceinline__ void acc_row(const float4* __restrict__ base4, int s, int c2,
                                        float4& a0, float4& a1) {
    const float4* p = base4 + (size_t)s * 16 + c2;
    float4 v0 = __ldg(p), v1 = __ldg(p + 1);
    a0.x += v0.x; a0.y += v0.y; a0.z += v0.z; a0.w += v0.w;
    a1.x += v1.x; a1.y += v1.y; a1.z += v1.z; a1.w += v1.w;
}

// Pull-aggregation layer 1: agg1[n] = sum over incoming edges of hs[src].
__global__ void aggregate1_kernel() {
    int tid = blockIdx.x * blockDim.x + threadIdx.x;
    int n = tid >> 3;
    if (n >= N_NODES) return;
    int c2 = (tid & 7) << 1;
    int i   = __ldg(&g_off[n]);
    int end = i + __ldg(&g_deg_in[n]);
    const float4* hs4 = reinterpret_cast<const float4*>(g_hs);
    float4 a0 = make_float4(0.f,0.f,0.f,0.f);
    float4 a1 = a0;
    while ((i & 3) && i < end) acc_row(hs4, __ldg(&g_esrc[i++]), c2, a0, a1);
    const int4* e4 = reinterpret_cast<const int4*>(g_esrc);
    for (; i + 4 <= end; i += 4) {
        int4 q = __ldg(&e4[i >> 2]);
        acc_row(hs4, q.x, c2, a0, a1);
        acc_row(hs4, q.y, c2, a0, a1);
        acc_row(hs4, q.z, c2, a0, a1);
        acc_row(hs4, q.w, c2, a0, a1);
    }
    for (; i < end; i++) acc_row(hs4, __ldg(&g_esrc[i]), c2, a0, a1);
    float4* o = reinterpret_cast<float4*>(g_agg1) + (size_t)n * 16 + c2;
    o[0] = a0; o[1] = a1;
}

// Fused persistent GEMM, 1024 threads, grid=148, 128-row tiles.
//   phase1: h1 = relu(norm_dst ⊙ (agg1 @ W1) + b1)  -> smem H1s (row-major)
//   phase2: t2 = norm_src ⊙ (h1 @ W2)               -> gmem
// A tile kept row-major; warp-level A reads are single-address broadcasts.
__global__ __launch_bounds__(1024) void fused_gemm_kernel(const float* __restrict__ W1,
                                                          const float* __restrict__ b1,
                                                          const float* __restrict__ W2) {
    extern __shared__ __align__(16) float sm[];
    float* Ws1 = sm + WS1_OFF;    // [k][col 128]
    float* Ws2 = sm + WS2_OFF;    // [k][col 64]
    float* As  = sm + AS_OFF;     // [row 128][k 64] row-major
    float* H1s = sm + H1_OFF;     // [row 128][col 128 pad 132] row-major
    int t = threadIdx.x;

    for (int i = t; i < F_IN * F_MID / 4; i += 1024)
        reinterpret_cast<float4*>(Ws1)[i] = __ldg(reinterpret_cast<const float4*>(W1) + i);
    for (int i = t; i < F_MID * F_IN / 4; i += 1024)
        reinterpret_cast<float4*>(Ws2)[i] = __ldg(reinterpret_cast<const float4*>(W2) + i);

    // phase1 mapping: cols 4*ct of 128, rows 4*rt of 128
    int ct = t & 31;
    int rt = t >> 5;       // 0..31
    // phase2 mapping: cols 4*ct2 of 64, rows 2*rt2 of 128
    int ct2 = t & 15;
    int rt2 = t >> 4;      // 0..63

    float4 bb = __ldg(reinterpret_cast<const float4*>(b1) + ct);

    for (int tile = blockIdx.x; tile < NTILES; tile += gridDim.x) {
        int row0 = tile * GTILE;
        __syncthreads();   // previous iteration fully done (As/H1s safe to overwrite)

        // Load A tile row-major (straight float4 copy, conflict-free)
        for (int i = t; i < GTILE * F_IN / 4; i += 1024) {
            int r  = i >> 4;            // 16 float4 per row
            int c4 = i & 15;
            int row = row0 + r;
            float4 v = (row < N_NODES)
                ? *reinterpret_cast<const float4*>(g_agg1 + (size_t)row * F_IN + (c4 << 2))
                : make_float4(0.f, 0.f, 0.f, 0.f);
            *reinterpret_cast<float4*>(&As[r * F_IN + (c4 << 2)]) = v;
        }
        __syncthreads();

        // ---- phase 1: 4 rows x 4 cols per thread, k unrolled by 4 ----
        float acc[4][4];
#pragma unroll
        for (int j = 0; j < 4; j++)
#pragma unroll
            for (int c = 0; c < 4; c++) acc[j][c] = 0.f;

        int rbase = rt << 2;
#pragma unroll 4
        for (int k4 = 0; k4 < F_IN / 4; k4++) {
            float4 a0 = *reinterpret_cast<const float4*>(&As[(rbase + 0) * F_IN + (k4 << 2)]);
            float4 a1 = *reinterpret_cast<const float4*>(&As[(rbase + 1) * F_IN + (k4 << 2)]);
            float4 a2 = *reinterpret_cast<const float4*>(&As[(rbase + 2) * F_IN + (k4 << 2)]);
            float4 a3 = *reinterpret_cast<const float4*>(&As[(rbase + 3) * F_IN + (k4 << 2)]);
#pragma unroll
            for (int kk = 0; kk < 4; kk++) {
                float4 w = *reinterpret_cast<const float4*>(&Ws1[((k4 << 2) + kk) * F_MID + (ct << 2)]);
                float av0 = kk == 0 ? a0.x : kk == 1 ? a0.y : kk == 2 ? a0.z : a0.w;
                float av1 = kk == 0 ? a1.x : kk == 1 ? a1.y : kk == 2 ? a1.z : a1.w;
                float av2 = kk == 0 ? a2.x : kk == 1 ? a2.y : kk == 2 ? a2.z : a2.w;
                float av3 = kk == 0 ? a3.x : kk == 1 ? a3.y : kk == 2 ? a3.z : a3.w;
                acc[0][0] = fmaf(av0, w.x, acc[0][0]); acc[0][1] = fmaf(av0, w.y, acc[0][1]);
                acc[0][2] = fmaf(av0, w.z, acc[0][2]); acc[0][3] = fmaf(av0, w.w, acc[0][3]);
                acc[1][0] = fmaf(av1, w.x, acc[1][0]); acc[1][1] = fmaf(av1, w.y, acc[1][1]);
                acc[1][2] = fmaf(av1, w.z, acc[1][2]); acc[1][3] = fmaf(av1, w.w, acc[1][3]);
                acc[2][0] = fmaf(av2, w.x, acc[2][0]); acc[2][1] = fmaf(av2, w.y, acc[2][1]);
                acc[2][2] = fmaf(av2, w.z, acc[2][2]); acc[2][3] = fmaf(av2, w.w, acc[2][3]);
                acc[3][0] = fmaf(av3, w.x, acc[3][0]); acc[3][1] = fmaf(av3, w.y, acc[3][1]);
                acc[3][2] = fmaf(av3, w.z, acc[3][2]); acc[3][3] = fmaf(av3, w.w, acc[3][3]);
            }
        }
#pragma unroll
        for (int j = 0; j < 4; j++) {
            int lr = rbase + j;
            int row = row0 + lr;
            float nd = (row < N_NODES) ? __ldg(&g_norm_dst[row]) : 0.f;
            float4 o;
            o.x = fmaxf(fmaf(acc[j][0], nd, bb.x), 0.f);
            o.y = fmaxf(fmaf(acc[j][1], nd, bb.y), 0.f);
            o.z = fmaxf(fmaf(acc[j][2], nd, bb.z), 0.f);
            o.w = fmaxf(fmaf(acc[j][3], nd, bb.w), 0.f);
            *reinterpret_cast<float4*>(&H1s[lr * 132 + (ct << 2)]) = o;
        }
        __syncthreads();

        // ---- phase 2: 2 rows x 4 cols per thread, k unrolled by 4 ----
        float acc2[2][4];
#pragma unroll
        for (int j = 0; j < 2; j++)
#pragma unroll
            for (int c = 0; c < 4; c++) acc2[j][c] = 0.f;

        int r0 = rt2 << 1;
#pragma unroll 4
        for (int k4 = 0; k4 < F_MID / 4; k4++) {
            float4 a0v = *reinterpret_cast<const float4*>(&H1s[r0 * 132 + (k4 << 2)]);
            float4 a1v = *reinterpret_cast<const float4*>(&H1s[(r0 + 1) * 132 + (k4 << 2)]);
#pragma unroll
            for (int kk = 0; kk < 4; kk++) {
                float4 w = *reinterpret_cast<const float4*>(&Ws2[((k4 << 2) + kk) * F_IN + (ct2 << 2)]);
                float av0 = kk == 0 ? a0v.x : kk == 1 ? a0v.y : kk == 2 ? a0v.z : a0v.w;
                float av1 = kk == 0 ? a1v.x : kk == 1 ? a1v.y : kk == 2 ? a1v.z : a1v.w;
                acc2[0][0] = fmaf(av0, w.x, acc2[0][0]); acc2[0][1] = fmaf(av0, w.y, acc2[0][1]);
                acc2[0][2] = fmaf(av0, w.z, acc2[0][2]); acc2[0][3] = fmaf(av0, w.w, acc2[0][3]);
                acc2[1][0] = fmaf(av1, w.x, acc2[1][0]); acc2[1][1] = fmaf(av1, w.y, acc2[1][1]);
                acc2[1][2] = fmaf(av1, w.z, acc2[1][2]); acc2[1][3] = fmaf(av1, w.w, acc2[1][3]);
            }
        }
#pragma unroll
        for (int j = 0; j < 2; j++) {
            int row = row0 + r0 + j;
            if (row < N_NODES) {
                float ns = __ldg(&g_norm_src[row]);
                float4 o;
                o.x = acc2[j][0] * ns; o.y = acc2[j][1] * ns;
                o.z = acc2[j][2] * ns; o.w = acc2[j][3] * ns;
                *reinterpret_cast<float4*>(g_t2 + (size_t)row * F_IN + (ct2 << 2)) = o;
            }
        }
    }
}

// Pull-aggregation layer 2 + fused epilogue: out[n] = (sum t2[src]) * norm_dst[n] + b2
__global__ void aggregate2_kernel(const float* __restrict__ b2,
                                  float* __restrict__ out) {
    int tid = blockIdx.x * blockDim.x + threadIdx.x;
    int n = tid >> 3;
    if (n >= N_NODES) return;
    int c2 = (tid & 7) << 1;
    int i   = __ldg(&g_off[n]);
    int end = i + __ldg(&g_deg_in[n]);
    const float4* t4 = reinterpret_cast<const float4*>(g_t2);
    float4 a0 = make_float4(0.f,0.f,0.f,0.f);
    float4 a1 = a0;
    while ((i & 3) && i < end) acc_row(t4, __ldg(&g_esrc[i++]), c2, a0, a1);
    const int4* e4 = reinterpret_cast<const int4*>(g_esrc);
    for (; i + 4 <= end; i += 4) {
        int4 q = __ldg(&e4[i >> 2]);
        acc_row(t4, q.x, c2, a0, a1);
        acc_row(t4, q.y, c2, a0, a1);
        acc_row(t4, q.z, c2, a0, a1);
        acc_row(t4, q.w, c2, a0, a1);
    }
    for (; i < end; i++) acc_row(t4, __ldg(&g_esrc[i]), c2, a0, a1);

    float nd = g_norm_dst[n];
    float4 b0 = reinterpret_cast<const float4*>(b2)[c2];
    float4 b1v = reinterpret_cast<const float4*>(b2)[c2 + 1];
    float4 o0, o1;
    o0.x = fmaf(a0.x, nd, b0.x);  o0.y = fmaf(a0.y, nd, b0.y);
    o0.z = fmaf(a0.z, nd, b0.z);  o0.w = fmaf(a0.w, nd, b0.w);
    o1.x = fmaf(a1.x, nd, b1v.x); o1.y = fmaf(a1.y, nd, b1v.y);
    o1.z = fmaf(a1.z, nd, b1v.z); o1.w = fmaf(a1.w, nd, b1v.w);
    float4* o = reinterpret_cast<float4*>(out) + (size_t)n * 16 + c2;
    o[0] = o0; o[1] = o1;
}

// ---------------- launch ----------------
extern "C" void kernel_launch(void* const* d_in, const int* in_sizes, int n_in,
                              void* d_out, int out_size) {
    const float* h   = (const float*)d_in[0];
    const int*   src = (const int*)  d_in[1];
    const int*   dst = (const int*)  d_in[2];
    const float* W1  = (const float*)d_in[3];
    const float* b1  = (const float*)d_in[4];
    const float* W2  = (const float*)d_in[5];
    const float* b2  = (const float*)d_in[6];
    float* out = (float*)d_out;

    cudaFuncSetAttribute(fused_gemm_kernel,
                         cudaFuncAttributeMaxDynamicSharedMemorySize, SMEM_BYTES);

    zero_kernel<<<(N_NODES + 255) / 256, 256>>>();
    degree_kernel<<<(N_EDGES / 2 + 255) / 256, 256>>>(src, dst);
    norm_offset_prescale_kernel<<<(N_NODES + 255) / 256, 256>>>(h);
    fill_kernel<<<(N_EDGES / 2 + 255) / 256, 256>>>(src, dst);

    const int a_threads = N_NODES * 8;
    aggregate1_kernel<<<(a_threads + 255) / 256, 256>>>();

    fused_gemm_kernel<<<148, 1024, SMEM_BYTES>>>(W1, b1, W2);

    aggregate2_kernel<<<(a_threads + 255) / 256, 256>>>(b2, out);
}